// round 13
// baseline (speedup 1.0000x reference)
#include <cuda_runtime.h>
#include <cuda_fp16.h>
#include <cstdint>
#include <cstddef>

#define BATCH   8192
#define IN_DIM  4096
#define HID     16384
#define KSEL    64
#define HB      520          // per-row histogram stride (513 used)

// -------- scratch (allocation-free: __device__ globals) --------
__device__ __half    g_wdecT[(size_t)HID * IN_DIM];  // W_dec^T fp16 [HID, IN_DIM]
__device__ float     g_vals[BATCH * KSEL];
__device__ int       g_idx [BATCH * KSEL];
__device__ __half    g_xh[(size_t)BATCH * IN_DIM];   // fp16(x)
__device__ __half    g_wh[(size_t)HID * IN_DIM];     // fp16(W_enc)
__device__ uint32_t  g_hist[(size_t)BATCH * HB];     // per-row feature histograms

// ============================================================================
// zero per-row histograms
// ============================================================================
__global__ __launch_bounds__(1024) void zero_hist_kernel()
{
    size_t i = (size_t)blockIdx.x * 1024 + threadIdx.x;
    if (i < (size_t)BATCH * HB) g_hist[i] = 0u;
}

// ============================================================================
// fp32 -> fp16 conversion
// ============================================================================
__global__ __launch_bounds__(256) void to_half_kernel(
    const float* __restrict__ src, __half* __restrict__ dst, size_t n4)
{
    size_t i = (size_t)blockIdx.x * 256 + threadIdx.x;
    if (i >= n4) return;
    float4 v = ((const float4*)src)[i];
    __half2* d = (__half2*)dst;
    d[2 * i]     = __floats2half2_rn(v.x, v.y);
    d[2 * i + 1] = __floats2half2_rn(v.z, v.w);
}

// ============================================================================
// transpose W_dec [IN_DIM, HID] -> g_wdecT (fp16) [HID, IN_DIM]
// ============================================================================
__global__ void wdec_transpose(const float* __restrict__ W)
{
    __shared__ float tile[32][33];
    int h0 = blockIdx.x * 32;
    int d0 = blockIdx.y * 32;
    int tx = threadIdx.x, ty = threadIdx.y;
#pragma unroll
    for (int r = 0; r < 32; r += 8)
        tile[ty + r][tx] = W[(size_t)(d0 + ty + r) * HID + (h0 + tx)];
    __syncthreads();
#pragma unroll
    for (int r = 0; r < 32; r += 8)
        g_wdecT[(size_t)(h0 + ty + r) * IN_DIM + (d0 + tx)] =
            __float2half_rn(tile[tx][ty + r]);
}

// ============================================================================
// Encoder GEMM: fp16 HMMA, fp32 accum; epilogue also builds per-row histograms
//   BM=128, BN=128, BK=64, 8 warps, warp tile 64x32, 3-stage, 2 CTAs/SM.
// ============================================================================
#define GBM 128
#define GBN 128
#define GBK 64
#define NSTAGE 3
#define ROWB 144
#define A_ST_B (GBM * ROWB)
#define B_ST_B (GBN * ROWB)
#define STG_B  (A_ST_B + B_ST_B)
#define GEMM_SMEM (NSTAGE * STG_B)   // 110592
#define K_ITERS (IN_DIM / GBK)
#define GEMM_THREADS 256

__device__ __forceinline__ uint32_t smem_u32(const void* p) {
    uint32_t a;
    asm("{ .reg .u64 t; cvta.to.shared.u64 t, %1; cvt.u32.u64 %0, t; }" : "=r"(a) : "l"(p));
    return a;
}
#define CP_ASYNC16(dst, src) \
    asm volatile("cp.async.cg.shared.global [%0], [%1], 16;" :: "r"(dst), "l"(src))
#define CP_COMMIT() asm volatile("cp.async.commit_group;" ::: "memory")
#define CP_WAIT1()  asm volatile("cp.async.wait_group 1;" ::: "memory")

#define LDSM_X4(r0, r1, r2, r3, addr) \
    asm volatile("ldmatrix.sync.aligned.m8n8.x4.shared.b16 {%0,%1,%2,%3}, [%4];" \
                 : "=r"(r0), "=r"(r1), "=r"(r2), "=r"(r3) : "r"(addr))

#define MMA16816(d, a, b0, b1) \
    asm volatile("mma.sync.aligned.m16n8k16.row.col.f32.f16.f16.f32 " \
                 "{%0,%1,%2,%3}, {%4,%5,%6,%7}, {%8,%9}, {%0,%1,%2,%3};" \
                 : "+f"((d)[0]), "+f"((d)[1]), "+f"((d)[2]), "+f"((d)[3]) \
                 : "r"((a)[0]), "r"((a)[1]), "r"((a)[2]), "r"((a)[3]), \
                   "r"(b0), "r"(b1))

__device__ __forceinline__ void hist_acc(int row, float f)
{
    if (f >= 2.0f) {
        uint32_t bin = (__float_as_uint(f) >> 15) - 0x8000u;
        if (bin > 512u) bin = 512u;           // >= 8.0 bucket
        atomicAdd(&g_hist[(size_t)row * HB + bin], 1u);
    }
}

__device__ __forceinline__ void gemm_load_stage(uint32_t sbase, int stage, int k0,
                                                int m0, int n0, int tid)
{
    uint32_t sb = sbase + stage * STG_B;
#pragma unroll
    for (int t = 0; t < 4; t++) {
        int i = tid + t * GEMM_THREADS;
        int row = i >> 3, c = i & 7;
        const __half* src = g_xh + (size_t)(m0 + row) * IN_DIM + k0 + c * 8;
        CP_ASYNC16(sb + row * ROWB + c * 16, src);
    }
    uint32_t sbB = sb + A_ST_B;
#pragma unroll
    for (int t = 0; t < 4; t++) {
        int i = tid + t * GEMM_THREADS;
        int row = i >> 3, c = i & 7;
        const __half* src = g_wh + (size_t)(n0 + row) * IN_DIM + k0 + c * 8;
        CP_ASYNC16(sbB + row * ROWB + c * 16, src);
    }
}

__global__ __launch_bounds__(GEMM_THREADS, 2) void encoder_gemm_hmma(
    const float* __restrict__ bias, float* __restrict__ out_sf)
{
    extern __shared__ __align__(128) char smem[];
    uint32_t sbase = smem_u32(smem);
    const int tid  = threadIdx.x;
    const int lane = tid & 31;
    const int wid  = tid >> 5;
    const int warp_m = wid & 1;
    const int warp_n = wid >> 1;

    int pid = blockIdx.x;
    int nb = (pid >> 3) & 127;
    int mb = (pid & 7) | ((pid >> 10) << 3);
    int m0 = mb * GBM, n0 = nb * GBN;

    const int g = lane >> 3;
    const int rA = warp_m * 64 + ((g & 1) << 3) + (lane & 7);
    const int cA = (g >> 1) << 4;
    const int rB = warp_n * 32 + ((g >> 1) << 3) + (lane & 7);
    const int cB = (g & 1) << 4;

    float acc[4][4][4];
#pragma unroll
    for (int i = 0; i < 4; i++)
#pragma unroll
        for (int j = 0; j < 4; j++)
#pragma unroll
            for (int q = 0; q < 4; q++) acc[i][j][q] = 0.0f;

    gemm_load_stage(sbase, 0, 0, m0, n0, tid); CP_COMMIT();
    gemm_load_stage(sbase, 1, GBK, m0, n0, tid); CP_COMMIT();

    for (int it = 0; it < K_ITERS; it++) {
        int cur = it % 3;
        CP_WAIT1();
        __syncthreads();

        if (it + 2 < K_ITERS)
            gemm_load_stage(sbase, (it + 2) % 3, (it + 2) * GBK, m0, n0, tid);
        CP_COMMIT();

        uint32_t aST = sbase + cur * STG_B;
        uint32_t bST = aST + A_ST_B;

#pragma unroll
        for (int ks = 0; ks < 4; ks++) {
            uint32_t koff = (uint32_t)(ks * 32);
            uint32_t af[4][4], bf[2][4];
#pragma unroll
            for (int mf = 0; mf < 4; mf++) {
                uint32_t ad = aST + (uint32_t)((rA + mf * 16) * ROWB + cA) + koff;
                LDSM_X4(af[mf][0], af[mf][1], af[mf][2], af[mf][3], ad);
            }
#pragma unroll
            for (int nf = 0; nf < 2; nf++) {
                uint32_t bd = bST + (uint32_t)((rB + nf * 16) * ROWB + cB) + koff;
                LDSM_X4(bf[nf][0], bf[nf][1], bf[nf][2], bf[nf][3], bd);
            }
#pragma unroll
            for (int mf = 0; mf < 4; mf++)
#pragma unroll
                for (int nf = 0; nf < 2; nf++) {
                    MMA16816(acc[mf][nf * 2],     af[mf], bf[nf][0], bf[nf][1]);
                    MMA16816(acc[mf][nf * 2 + 1], af[mf], bf[nf][2], bf[nf][3]);
                }
        }
    }

    // epilogue: bias + relu -> out_sf, plus per-row histogram accumulation
    int rbase = m0 + warp_m * 64 + (lane >> 2);
    int cbase = n0 + warp_n * 32 + ((lane & 3) << 1);
#pragma unroll
    for (int mf = 0; mf < 4; mf++) {
#pragma unroll
        for (int nf = 0; nf < 4; nf++) {
            int col = cbase + nf * 8;
            float b0 = __ldg(&bias[col]);
            float b1 = __ldg(&bias[col + 1]);
            int r0 = rbase + mf * 16;
            float2 v0, v1;
            v0.x = fmaxf(acc[mf][nf][0] + b0, 0.0f);
            v0.y = fmaxf(acc[mf][nf][1] + b1, 0.0f);
            v1.x = fmaxf(acc[mf][nf][2] + b0, 0.0f);
            v1.y = fmaxf(acc[mf][nf][3] + b1, 0.0f);
            *(float2*)(out_sf + (size_t)r0 * HID + col)       = v0;
            *(float2*)(out_sf + (size_t)(r0 + 8) * HID + col) = v1;
            hist_acc(r0, v0.x);     hist_acc(r0, v0.y);
            hist_acc(r0 + 8, v1.x); hist_acc(r0 + 8, v1.y);
        }
    }
}

// ============================================================================
// top-k v5: histogram precomputed by GEMM epilogue -> ONE full-row sweep.
//   R11's proven classify/refine/select/compact structure otherwise.
// ============================================================================
#define TOPK_THREADS 512
#define NBINS 1024
#define ERRB 3e-3f
#define ZCAP 128
#define NWORDS (HID / 32)    // 512

__device__ __forceinline__ float refine_dot_warp(const float* __restrict__ xr,
                                                 const float* __restrict__ wr,
                                                 float b, int lane)
{
    float s = 0.f, c = 0.f;
    for (int t = 0; t < 16; t++) {
        int base = t * 256 + lane;
        float r = xr[base] * wr[base];
#pragma unroll
        for (int j = 1; j < 8; j++)
            r = fmaf(xr[base + 32 * j], wr[base + 32 * j], r);
        float tt = s + r;
        float z = tt - s;
        float e = (s - (tt - z)) + (r - z);
        c += e; s = tt;
    }
#pragma unroll
    for (int off = 16; off; off >>= 1) {
        float s2 = __shfl_down_sync(0xffffffffu, s, off);
        float c2 = __shfl_down_sync(0xffffffffu, c, off);
        float tt = s + s2;
        float z = tt - s;
        float e = (s - (tt - z)) + (s2 - z);
        c += c2 + e; s = tt;
    }
    float d = s + c;
    return fmaxf(d + b, 0.0f);
}

__device__ __forceinline__ int scan_bins_top(const uint32_t* hist, int top,
                                             int base, int lane)
{
    int dbin = -1;
    int nrounds = (top + 31) / 32;
    for (int r = 0; r < nrounds; r++) {
        int bin = top - 1 - (r * 32 + lane);
        int h = (bin >= 0) ? (int)hist[bin] : 0;
        int pre = h;
#pragma unroll
        for (int off = 1; off < 32; off <<= 1) {
            int t = __shfl_up_sync(0xffffffffu, pre, off);
            if (lane >= off) pre += t;
        }
        int cum = base + pre;
        unsigned bal = __ballot_sync(0xffffffffu, (cum >= KSEL) && (bin >= 0));
        if (bal) {
            int l0 = __ffs(bal) - 1;
            dbin = top - 1 - (r * 32 + l0);
            break;
        }
        base += __shfl_sync(0xffffffffu, pre, 31);
    }
    return dbin;
}

__global__ __launch_bounds__(TOPK_THREADS) void topk_kernel(
    float* __restrict__ out_sf,
    const float* __restrict__ x,
    const float* __restrict__ W,
    const float* __restrict__ bias)
{
    __shared__ uint32_t hist[NBINS];
    __shared__ uint32_t keep[NWORDS];
    __shared__ int s_big, s_nhi, s_nzone, s_dbin, s_mode;
    __shared__ int   s_zidx[ZCAP];
    __shared__ float s_zval[ZCAP];
    __shared__ unsigned char s_keepz[ZCAP];
    __shared__ int s_wsum[16];

    int row = blockIdx.x;
    int tid = threadIdx.x;
    int wid = tid >> 5, lane = tid & 31;
    float* orow = out_sf + (size_t)row * HID;

    // load precomputed histogram (513 words; no row sweep needed)
    for (int i = tid; i < 513; i += TOPK_THREADS)
        hist[i] = g_hist[(size_t)row * HB + i];
    if (tid == 0) { s_nhi = 0; s_nzone = 0; s_dbin = -1; s_mode = 0; }
    __syncthreads();
    if (tid == 0) s_big = (int)hist[512];
    __syncthreads();

    if (wid == 0) {
        int d = scan_bins_top(hist, 512, s_big, lane);
        if (lane == 0) { s_dbin = d; if (d >= 0) s_mode = 1; }
    }
    __syncthreads();

    if (s_mode == 0) {
        // mode B (rare): row-sweep histogram [0.25, 8) on bits[30:16]
        hist[tid] = 0; hist[tid + TOPK_THREADS] = 0;
        __syncthreads();
        for (int i = tid; i < HID; i += TOPK_THREADS) {
            float f = orow[i];
            if (f >= 0.25f && f < 8.0f)
                atomicAdd(&hist[(__float_as_uint(f) >> 16) - 0x3E80u], 1u);
        }
        __syncthreads();
        if (wid == 0) {
            int d = scan_bins_top(hist, 640, s_big, lane);
            if (lane == 0) { s_dbin = d; if (d >= 0) s_mode = 2; else s_mode = 3; }
        }
        __syncthreads();
    }

    float B_lo, B_hi;
    if (s_mode == 1) {
        B_lo = __uint_as_float((uint32_t)(0x8000u + s_dbin) << 15);
        B_hi = __uint_as_float((uint32_t)(0x8000u + s_dbin + 1) << 15);
    } else if (s_mode == 2) {
        B_lo = __uint_as_float((uint32_t)(0x3E80u + s_dbin) << 16);
        B_hi = __uint_as_float((uint32_t)(0x3E80u + s_dbin + 1) << 16);
    } else {
        B_lo = 0.0f; B_hi = 0.25f;
    }
    float Thi = B_hi + 2.0f * ERRB;
    float Tlo = B_lo - 2.0f * ERRB;

    // single full-row sweep: classify + zero below-zone positives + keep bits
    {
        int myhi = 0;
        for (int w = wid; w < NWORDS; w += (TOPK_THREADS / 32)) {
            int i = w * 32 + lane;
            float f = orow[i];
            bool hi = (f > Thi);
            bool inz = false;
            if (!hi && f > 0.0f && f >= Tlo) {
                int p = atomicAdd(&s_nzone, 1);
                if (p < ZCAP) { s_zidx[p] = i; s_zval[p] = f; inz = true; }
            }
            myhi += hi;
            unsigned m = __ballot_sync(0xffffffffu, hi);
            if (lane == 0) keep[w] = m;
            if (!hi && !inz && __float_as_uint(f) != 0u) orow[i] = 0.0f;
        }
#pragma unroll
        for (int off = 16; off; off >>= 1) myhi += __shfl_down_sync(0xffffffffu, myhi, off);
        if (lane == 0 && myhi) atomicAdd(&s_nhi, myhi);
    }
    __syncthreads();

    int nhi  = s_nhi;
    int nzr  = s_nzone;
    bool ovf = (nzr > ZCAP);
    int nz   = ovf ? ZCAP : nzr;
    int need = KSEL - nhi;

    bool did_refine = (!ovf && nz != need && nz > 0 && need > 0);
    if (did_refine) {
        const float* xr = x + (size_t)row * IN_DIM;
        for (int j = wid; j < nz; j += (TOPK_THREADS / 32)) {
            int h = s_zidx[j];
            float v = refine_dot_warp(xr, W + (size_t)h * IN_DIM, __ldg(&bias[h]), lane);
            if (lane == 0) s_zval[j] = v;
        }
    }
    __syncthreads();

    // rank selection among zone (exact top-`need`, index tiebreak)
    if (tid < nz) {
        bool km;
        if (!ovf && nz == need) km = true;
        else if (need <= 0) km = false;
        else {
            float mv = s_zval[tid]; int mi = s_zidx[tid];
            int better = 0;
            for (int j = 0; j < nz; j++) {
                if (j == tid) continue;
                if (s_zval[j] > mv || (s_zval[j] == mv && s_zidx[j] < mi)) better++;
            }
            km = (better < need);
        }
        s_keepz[tid] = km ? 1 : 0;
    }
    __syncthreads();

    // patch zone elements
    if (tid < nz) {
        int i = s_zidx[tid];
        if (s_keepz[tid]) {
            orow[i] = s_zval[tid];
            atomicOr(&keep[i >> 5], 1u << (i & 31));
        } else {
            orow[i] = 0.0f;
        }
    }
    __syncthreads();

    // parallel compaction: block exclusive scan over keep-word popcounts
    {
        uint32_t m = keep[tid];
        int c = __popc(m);
        int pre = c;
#pragma unroll
        for (int off = 1; off < 32; off <<= 1) {
            int t = __shfl_up_sync(0xffffffffu, pre, off);
            if (lane >= off) pre += t;
        }
        if (lane == 31) s_wsum[wid] = pre;
        __syncthreads();
        if (wid == 0 && lane < 16) {
            int v = s_wsum[lane];
            int p = v;
#pragma unroll
            for (int off = 1; off < 16; off <<= 1) {
                int t = __shfl_up_sync(0xffffu, p, off);
                if (lane >= off) p += t;
            }
            s_wsum[lane] = p - v;
        }
        __syncthreads();
        int excl = s_wsum[wid] + pre - c;
        while (m) {
            int b = __ffs(m) - 1;
            m &= m - 1;
            if (excl < KSEL) {
                g_vals[row * KSEL + excl] = orow[tid * 32 + b];
                g_idx [row * KSEL + excl] = tid * 32 + b;
            }
            excl++;
        }
    }
}

// ============================================================================
// sparse decode  recon[b,:] = sum_j v_j * W_dec^T[h_j, :]  (fp16 weights)
// ============================================================================
__global__ __launch_bounds__(256) void decoder_kernel(float* __restrict__ out_rec)
{
    int row = blockIdx.x;
    int tid = threadIdx.x;
    __shared__ float sv[KSEL];
    __shared__ int   si[KSEL];
    if (tid < KSEL) { sv[tid] = g_vals[row * KSEL + tid]; si[tid] = g_idx[row * KSEL + tid]; }
    __syncthreads();

    float acc[16];
#pragma unroll
    for (int q = 0; q < 16; q++) acc[q] = 0.0f;

    for (int j = 0; j < KSEL; j++) {
        float v = sv[j];
        const uint4* wp = (const uint4*)(g_wdecT + (size_t)si[j] * IN_DIM);
#pragma unroll
        for (int w = 0; w < 2; w++) {
            uint4 t = wp[tid + w * 256];
            float2 f0 = __half22float2(*(__half2*)&t.x);
            float2 f1 = __half22float2(*(__half2*)&t.y);
            float2 f2 = __half22float2(*(__half2*)&t.z);
            float2 f3 = __half22float2(*(__half2*)&t.w);
            acc[w*8+0] = fmaf(v, f0.x, acc[w*8+0]);
            acc[w*8+1] = fmaf(v, f0.y, acc[w*8+1]);
            acc[w*8+2] = fmaf(v, f1.x, acc[w*8+2]);
            acc[w*8+3] = fmaf(v, f1.y, acc[w*8+3]);
            acc[w*8+4] = fmaf(v, f2.x, acc[w*8+4]);
            acc[w*8+5] = fmaf(v, f2.y, acc[w*8+5]);
            acc[w*8+6] = fmaf(v, f3.x, acc[w*8+6]);
            acc[w*8+7] = fmaf(v, f3.y, acc[w*8+7]);
        }
    }
    float* op = out_rec + (size_t)row * IN_DIM;
#pragma unroll
    for (int w = 0; w < 2; w++) {
        *(float4*)(op + (tid + w * 256) * 8)     = *(float4*)(&acc[w*8]);
        *(float4*)(op + (tid + w * 256) * 8 + 4) = *(float4*)(&acc[w*8+4]);
    }
}

// ============================================================================
// launch
// ============================================================================
extern "C" void kernel_launch(void* const* d_in, const int* in_sizes, int n_in,
                              void* d_out, int out_size)
{
    const float* x     = (const float*)d_in[0];
    const float* W_enc = (const float*)d_in[1];
    const float* b_enc = (const float*)d_in[2];
    const float* W_dec = (const float*)d_in[3];

    float* out_sf  = (float*)d_out;
    float* out_rec = out_sf + (size_t)BATCH * HID;

    __half *xh, *wh;
    cudaGetSymbolAddress((void**)&xh, g_xh);
    cudaGetSymbolAddress((void**)&wh, g_wh);

    // 0) zero per-row histograms
    zero_hist_kernel<<<((unsigned)((size_t)BATCH * HB + 1023) / 1024), 1024>>>();

    // 1) fp16 conversions
    size_t nx4 = (size_t)BATCH * IN_DIM / 4;
    size_t nw4 = (size_t)HID * IN_DIM / 4;
    to_half_kernel<<<(unsigned)(nx4 / 256), 256>>>(x, xh, nx4);
    to_half_kernel<<<(unsigned)(nw4 / 256), 256>>>(W_enc, wh, nw4);

    // 2) transpose W_dec -> fp16
    wdec_transpose<<<dim3(HID / 32, IN_DIM / 32), dim3(32, 8)>>>(W_dec);

    // 3) encoder GEMM (HMMA, 2 CTAs/SM) + in-epilogue histograms -> out_sf
    cudaFuncSetAttribute(encoder_gemm_hmma, cudaFuncAttributeMaxDynamicSharedMemorySize,
                         GEMM_SMEM);
    encoder_gemm_hmma<<<(HID / GBN) * (BATCH / GBM), GEMM_THREADS, GEMM_SMEM>>>(b_enc, out_sf);

    // 4) top-k v5 (bracket from precomputed hist, one row sweep)
    topk_kernel<<<BATCH, TOPK_THREADS>>>(out_sf, x, W_enc, b_enc);

    // 5) sparse decode (fp16 weights)
    decoder_kernel<<<BATCH, 256>>>(out_rec);
}

// round 14
// speedup vs baseline: 1.0458x; 1.0458x over previous
#include <cuda_runtime.h>
#include <cuda_fp16.h>
#include <cstdint>
#include <cstddef>

#define BATCH   8192
#define IN_DIM  4096
#define HID     16384
#define KSEL    64

// -------- scratch (allocation-free: __device__ globals) --------
__device__ __half g_wdecT[(size_t)HID * IN_DIM];     // W_dec^T in fp16 [HID, IN_DIM]
__device__ float  g_vals[BATCH * KSEL];
__device__ int    g_idx [BATCH * KSEL];
__device__ __half g_xh[(size_t)BATCH * IN_DIM];      // fp16(x)
__device__ __half g_wh[(size_t)HID * IN_DIM];        // fp16(W_enc)

// ============================================================================
// fp32 -> fp16 conversion
// ============================================================================
__global__ __launch_bounds__(256) void to_half_kernel(
    const float* __restrict__ src, __half* __restrict__ dst, size_t n4)
{
    size_t i = (size_t)blockIdx.x * 256 + threadIdx.x;
    if (i >= n4) return;
    float4 v = ((const float4*)src)[i];
    __half2* d = (__half2*)dst;
    d[2 * i]     = __floats2half2_rn(v.x, v.y);
    d[2 * i + 1] = __floats2half2_rn(v.z, v.w);
}

// ============================================================================
// transpose W_dec [IN_DIM, HID] -> g_wdecT (fp16) [HID, IN_DIM]
// ============================================================================
__global__ void wdec_transpose(const float* __restrict__ W)
{
    __shared__ float tile[32][33];
    int h0 = blockIdx.x * 32;
    int d0 = blockIdx.y * 32;
    int tx = threadIdx.x, ty = threadIdx.y;
#pragma unroll
    for (int r = 0; r < 32; r += 8)
        tile[ty + r][tx] = W[(size_t)(d0 + ty + r) * HID + (h0 + tx)];
    __syncthreads();
#pragma unroll
    for (int r = 0; r < 32; r += 8)
        g_wdecT[(size_t)(h0 + ty + r) * IN_DIM + (d0 + tx)] =
            __float2half_rn(tile[tx][ty + r]);
}

// ============================================================================
// Encoder GEMM: fp16 HMMA, fp32 accum (R11 proven config, NO epilogue atomics)
//   BM=128, BN=128, BK=64, 8 warps, warp tile 64x32, 3-stage, 2 CTAs/SM.
// ============================================================================
#define GBM 128
#define GBN 128
#define GBK 64
#define NSTAGE 3
#define ROWB 144
#define A_ST_B (GBM * ROWB)
#define B_ST_B (GBN * ROWB)
#define STG_B  (A_ST_B + B_ST_B)
#define GEMM_SMEM (NSTAGE * STG_B)   // 110592
#define K_ITERS (IN_DIM / GBK)
#define GEMM_THREADS 256

__device__ __forceinline__ uint32_t smem_u32(const void* p) {
    uint32_t a;
    asm("{ .reg .u64 t; cvta.to.shared.u64 t, %1; cvt.u32.u64 %0, t; }" : "=r"(a) : "l"(p));
    return a;
}
#define CP_ASYNC16(dst, src) \
    asm volatile("cp.async.cg.shared.global [%0], [%1], 16;" :: "r"(dst), "l"(src))
#define CP_COMMIT() asm volatile("cp.async.commit_group;" ::: "memory")
#define CP_WAIT1()  asm volatile("cp.async.wait_group 1;" ::: "memory")

#define LDSM_X4(r0, r1, r2, r3, addr) \
    asm volatile("ldmatrix.sync.aligned.m8n8.x4.shared.b16 {%0,%1,%2,%3}, [%4];" \
                 : "=r"(r0), "=r"(r1), "=r"(r2), "=r"(r3) : "r"(addr))

#define MMA16816(d, a, b0, b1) \
    asm volatile("mma.sync.aligned.m16n8k16.row.col.f32.f16.f16.f32 " \
                 "{%0,%1,%2,%3}, {%4,%5,%6,%7}, {%8,%9}, {%0,%1,%2,%3};" \
                 : "+f"((d)[0]), "+f"((d)[1]), "+f"((d)[2]), "+f"((d)[3]) \
                 : "r"((a)[0]), "r"((a)[1]), "r"((a)[2]), "r"((a)[3]), \
                   "r"(b0), "r"(b1))

__device__ __forceinline__ void gemm_load_stage(uint32_t sbase, int stage, int k0,
                                                int m0, int n0, int tid)
{
    uint32_t sb = sbase + stage * STG_B;
#pragma unroll
    for (int t = 0; t < 4; t++) {
        int i = tid + t * GEMM_THREADS;
        int row = i >> 3, c = i & 7;
        const __half* src = g_xh + (size_t)(m0 + row) * IN_DIM + k0 + c * 8;
        CP_ASYNC16(sb + row * ROWB + c * 16, src);
    }
    uint32_t sbB = sb + A_ST_B;
#pragma unroll
    for (int t = 0; t < 4; t++) {
        int i = tid + t * GEMM_THREADS;
        int row = i >> 3, c = i & 7;
        const __half* src = g_wh + (size_t)(n0 + row) * IN_DIM + k0 + c * 8;
        CP_ASYNC16(sbB + row * ROWB + c * 16, src);
    }
}

__global__ __launch_bounds__(GEMM_THREADS, 2) void encoder_gemm_hmma(
    const float* __restrict__ bias, float* __restrict__ out_sf)
{
    extern __shared__ __align__(128) char smem[];
    uint32_t sbase = smem_u32(smem);
    const int tid  = threadIdx.x;
    const int lane = tid & 31;
    const int wid  = tid >> 5;
    const int warp_m = wid & 1;
    const int warp_n = wid >> 1;

    int pid = blockIdx.x;
    int nb = (pid >> 3) & 127;
    int mb = (pid & 7) | ((pid >> 10) << 3);
    int m0 = mb * GBM, n0 = nb * GBN;

    const int g = lane >> 3;
    const int rA = warp_m * 64 + ((g & 1) << 3) + (lane & 7);
    const int cA = (g >> 1) << 4;
    const int rB = warp_n * 32 + ((g >> 1) << 3) + (lane & 7);
    const int cB = (g & 1) << 4;

    float acc[4][4][4];
#pragma unroll
    for (int i = 0; i < 4; i++)
#pragma unroll
        for (int j = 0; j < 4; j++)
#pragma unroll
            for (int q = 0; q < 4; q++) acc[i][j][q] = 0.0f;

    gemm_load_stage(sbase, 0, 0, m0, n0, tid); CP_COMMIT();
    gemm_load_stage(sbase, 1, GBK, m0, n0, tid); CP_COMMIT();

    for (int it = 0; it < K_ITERS; it++) {
        int cur = it % 3;
        CP_WAIT1();
        __syncthreads();

        if (it + 2 < K_ITERS)
            gemm_load_stage(sbase, (it + 2) % 3, (it + 2) * GBK, m0, n0, tid);
        CP_COMMIT();

        uint32_t aST = sbase + cur * STG_B;
        uint32_t bST = aST + A_ST_B;

#pragma unroll
        for (int ks = 0; ks < 4; ks++) {
            uint32_t koff = (uint32_t)(ks * 32);
            uint32_t af[4][4], bf[2][4];
#pragma unroll
            for (int mf = 0; mf < 4; mf++) {
                uint32_t ad = aST + (uint32_t)((rA + mf * 16) * ROWB + cA) + koff;
                LDSM_X4(af[mf][0], af[mf][1], af[mf][2], af[mf][3], ad);
            }
#pragma unroll
            for (int nf = 0; nf < 2; nf++) {
                uint32_t bd = bST + (uint32_t)((rB + nf * 16) * ROWB + cB) + koff;
                LDSM_X4(bf[nf][0], bf[nf][1], bf[nf][2], bf[nf][3], bd);
            }
#pragma unroll
            for (int mf = 0; mf < 4; mf++)
#pragma unroll
                for (int nf = 0; nf < 2; nf++) {
                    MMA16816(acc[mf][nf * 2],     af[mf], bf[nf][0], bf[nf][1]);
                    MMA16816(acc[mf][nf * 2 + 1], af[mf], bf[nf][2], bf[nf][3]);
                }
        }
    }

    int rbase = m0 + warp_m * 64 + (lane >> 2);
    int cbase = n0 + warp_n * 32 + ((lane & 3) << 1);
#pragma unroll
    for (int mf = 0; mf < 4; mf++) {
#pragma unroll
        for (int nf = 0; nf < 4; nf++) {
            int col = cbase + nf * 8;
            float b0 = __ldg(&bias[col]);
            float b1 = __ldg(&bias[col + 1]);
            int r0 = rbase + mf * 16;
            float2 v0, v1;
            v0.x = fmaxf(acc[mf][nf][0] + b0, 0.0f);
            v0.y = fmaxf(acc[mf][nf][1] + b1, 0.0f);
            v1.x = fmaxf(acc[mf][nf][2] + b0, 0.0f);
            v1.y = fmaxf(acc[mf][nf][3] + b1, 0.0f);
            *(float2*)(out_sf + (size_t)r0 * HID + col)       = v0;
            *(float2*)(out_sf + (size_t)(r0 + 8) * HID + col) = v1;
        }
    }
}

// ============================================================================
// top-k v4 (R11 proven) with HIGH-MLP exact refinement:
//   refine_dot_warp now batches 8 float4 loads per step (MLP 8 vs 2),
//   cutting the refine critical path ~4x.
// ============================================================================
#define TOPK_THREADS 512
#define NBINS 1024
#define ERRB 3e-3f
#define ZCAP 128
#define NWORDS (HID / 32)    // 512

__device__ __forceinline__ float refine_dot_warp(const float* __restrict__ xr,
                                                 const float* __restrict__ wr,
                                                 float b, int lane)
{
    const float4* x4 = (const float4*)xr;
    const float4* w4 = (const float4*)wr;
    float s = 0.f, c = 0.f;
#pragma unroll
    for (int t = 0; t < 8; t++) {
        float4 xa[4], wa[4];
#pragma unroll
        for (int q = 0; q < 4; q++) {
            int idx = lane + (t * 4 + q) * 32;
            xa[q] = x4[idx];
            wa[q] = w4[idx];
        }
        float r = xa[0].x * wa[0].x;
        r = fmaf(xa[0].y, wa[0].y, r);
        r = fmaf(xa[0].z, wa[0].z, r);
        r = fmaf(xa[0].w, wa[0].w, r);
#pragma unroll
        for (int q = 1; q < 4; q++) {
            r = fmaf(xa[q].x, wa[q].x, r);
            r = fmaf(xa[q].y, wa[q].y, r);
            r = fmaf(xa[q].z, wa[q].z, r);
            r = fmaf(xa[q].w, wa[q].w, r);
        }
        float tt = s + r;
        float z = tt - s;
        float e = (s - (tt - z)) + (r - z);
        c += e; s = tt;
    }
#pragma unroll
    for (int off = 16; off; off >>= 1) {
        float s2 = __shfl_down_sync(0xffffffffu, s, off);
        float c2 = __shfl_down_sync(0xffffffffu, c, off);
        float tt = s + s2;
        float z = tt - s;
        float e = (s - (tt - z)) + (s2 - z);
        c += c2 + e; s = tt;
    }
    float d = s + c;
    return fmaxf(d + b, 0.0f);
}

__device__ __forceinline__ int scan_bins_top(const uint32_t* hist, int top,
                                             int base, int lane)
{
    int dbin = -1;
    int nrounds = (top + 31) / 32;
    for (int r = 0; r < nrounds; r++) {
        int bin = top - 1 - (r * 32 + lane);
        int h = (bin >= 0) ? (int)hist[bin] : 0;
        int pre = h;
#pragma unroll
        for (int off = 1; off < 32; off <<= 1) {
            int t = __shfl_up_sync(0xffffffffu, pre, off);
            if (lane >= off) pre += t;
        }
        int cum = base + pre;
        unsigned bal = __ballot_sync(0xffffffffu, (cum >= KSEL) && (bin >= 0));
        if (bal) {
            int l0 = __ffs(bal) - 1;
            dbin = top - 1 - (r * 32 + l0);
            break;
        }
        base += __shfl_sync(0xffffffffu, pre, 31);
    }
    return dbin;
}

__global__ __launch_bounds__(TOPK_THREADS) void topk_kernel(
    float* __restrict__ out_sf,
    const float* __restrict__ x,
    const float* __restrict__ W,
    const float* __restrict__ bias)
{
    __shared__ uint32_t hist[NBINS];
    __shared__ uint32_t keep[NWORDS];
    __shared__ int s_big, s_nhi, s_nzone, s_dbin, s_mode;
    __shared__ int   s_zidx[ZCAP];
    __shared__ float s_zval[ZCAP];
    __shared__ unsigned char s_keepz[ZCAP];
    __shared__ int s_wsum[16];

    int row = blockIdx.x;
    int tid = threadIdx.x;
    int wid = tid >> 5, lane = tid & 31;
    float* orow = out_sf + (size_t)row * HID;

    hist[tid] = 0; hist[tid + TOPK_THREADS] = 0;
    if (tid == 0) { s_big = 0; s_nhi = 0; s_nzone = 0; s_dbin = -1; s_mode = 0; }
    __syncthreads();

    // sweep 1: read row (coalesced float4, DRAM) + histogram on [2,8)
    int mybig = 0;
#pragma unroll
    for (int t = 0; t < 8; t++) {
        float4 v4 = ((const float4*)orow)[tid + t * TOPK_THREADS];
        float vv[4] = {v4.x, v4.y, v4.z, v4.w};
#pragma unroll
        for (int c = 0; c < 4; c++) {
            float f = vv[c];
            if (f >= 8.0f) mybig++;
            else if (f >= 2.0f)
                atomicAdd(&hist[(__float_as_uint(f) >> 15) - 0x8000u], 1u);
        }
    }
#pragma unroll
    for (int off = 16; off; off >>= 1) mybig += __shfl_down_sync(0xffffffffu, mybig, off);
    if (lane == 0 && mybig) atomicAdd(&s_big, mybig);
    __syncthreads();

    if (wid == 0) {
        int d = scan_bins_top(hist, 512, s_big, lane);
        if (lane == 0) { s_dbin = d; if (d >= 0) s_mode = 1; }
    }
    __syncthreads();

    if (s_mode == 0) {
        // mode B (rare): histogram [0.25, 8) on bits[30:16]
        hist[tid] = 0; hist[tid + TOPK_THREADS] = 0;
        __syncthreads();
        for (int i = tid; i < HID; i += TOPK_THREADS) {
            float f = orow[i];
            if (f >= 0.25f && f < 8.0f)
                atomicAdd(&hist[(__float_as_uint(f) >> 16) - 0x3E80u], 1u);
        }
        __syncthreads();
        if (wid == 0) {
            int d = scan_bins_top(hist, 640, s_big, lane);
            if (lane == 0) { s_dbin = d; if (d >= 0) s_mode = 2; else s_mode = 3; }
        }
        __syncthreads();
    }

    float B_lo, B_hi;
    if (s_mode == 1) {
        B_lo = __uint_as_float((uint32_t)(0x8000u + s_dbin) << 15);
        B_hi = __uint_as_float((uint32_t)(0x8000u + s_dbin + 1) << 15);
    } else if (s_mode == 2) {
        B_lo = __uint_as_float((uint32_t)(0x3E80u + s_dbin) << 16);
        B_hi = __uint_as_float((uint32_t)(0x3E80u + s_dbin + 1) << 16);
    } else {
        B_lo = 0.0f; B_hi = 0.25f;
    }
    float Thi = B_hi + 2.0f * ERRB;
    float Tlo = B_lo - 2.0f * ERRB;

    // sweep 2 (L2-hot): classify + zero below-zone positives + provisional keep
    {
        int myhi = 0;
        for (int w = wid; w < NWORDS; w += (TOPK_THREADS / 32)) {
            int i = w * 32 + lane;
            float f = orow[i];
            bool hi = (f > Thi);
            bool inz = false;
            if (!hi && f > 0.0f && f >= Tlo) {
                int p = atomicAdd(&s_nzone, 1);
                if (p < ZCAP) { s_zidx[p] = i; s_zval[p] = f; inz = true; }
            }
            myhi += hi;
            unsigned m = __ballot_sync(0xffffffffu, hi);
            if (lane == 0) keep[w] = m;
            if (!hi && !inz && __float_as_uint(f) != 0u) orow[i] = 0.0f;
        }
#pragma unroll
        for (int off = 16; off; off >>= 1) myhi += __shfl_down_sync(0xffffffffu, myhi, off);
        if (lane == 0 && myhi) atomicAdd(&s_nhi, myhi);
    }
    __syncthreads();

    int nhi  = s_nhi;
    int nzr  = s_nzone;
    bool ovf = (nzr > ZCAP);
    int nz   = ovf ? ZCAP : nzr;
    int need = KSEL - nhi;

    bool did_refine = (!ovf && nz != need && nz > 0 && need > 0);
    if (did_refine) {
        const float* xr = x + (size_t)row * IN_DIM;
        for (int j = wid; j < nz; j += (TOPK_THREADS / 32)) {
            int h = s_zidx[j];
            float v = refine_dot_warp(xr, W + (size_t)h * IN_DIM, __ldg(&bias[h]), lane);
            if (lane == 0) s_zval[j] = v;
        }
    }
    __syncthreads();

    // rank selection among zone (exact top-`need`, index tiebreak)
    if (tid < nz) {
        bool km;
        if (!ovf && nz == need) km = true;
        else if (need <= 0) km = false;
        else {
            float mv = s_zval[tid]; int mi = s_zidx[tid];
            int better = 0;
            for (int j = 0; j < nz; j++) {
                if (j == tid) continue;
                if (s_zval[j] > mv || (s_zval[j] == mv && s_zidx[j] < mi)) better++;
            }
            km = (better < need);
        }
        s_keepz[tid] = km ? 1 : 0;
    }
    __syncthreads();

    // patch zone elements: kept -> (refined) value + keep bit; dropped -> 0
    if (tid < nz) {
        int i = s_zidx[tid];
        if (s_keepz[tid]) {
            orow[i] = s_zval[tid];
            atomicOr(&keep[i >> 5], 1u << (i & 31));
        } else {
            orow[i] = 0.0f;
        }
    }
    __syncthreads();

    // parallel compaction: block exclusive scan over keep-word popcounts
    {
        uint32_t m = keep[tid];
        int c = __popc(m);
        int pre = c;
#pragma unroll
        for (int off = 1; off < 32; off <<= 1) {
            int t = __shfl_up_sync(0xffffffffu, pre, off);
            if (lane >= off) pre += t;
        }
        if (lane == 31) s_wsum[wid] = pre;
        __syncthreads();
        if (wid == 0 && lane < 16) {
            int v = s_wsum[lane];
            int p = v;
#pragma unroll
            for (int off = 1; off < 16; off <<= 1) {
                int t = __shfl_up_sync(0xffffu, p, off);
                if (lane >= off) p += t;
            }
            s_wsum[lane] = p - v;
        }
        __syncthreads();
        int excl = s_wsum[wid] + pre - c;
        while (m) {
            int b = __ffs(m) - 1;
            m &= m - 1;
            if (excl < KSEL) {
                g_vals[row * KSEL + excl] = orow[tid * 32 + b];
                g_idx [row * KSEL + excl] = tid * 32 + b;
            }
            excl++;
        }
    }
}

// ============================================================================
// sparse decode  recon[b,:] = sum_j v_j * W_dec^T[h_j, :]  (fp16 weights)
// ============================================================================
__global__ __launch_bounds__(256) void decoder_kernel(float* __restrict__ out_rec)
{
    int row = blockIdx.x;
    int tid = threadIdx.x;
    __shared__ float sv[KSEL];
    __shared__ int   si[KSEL];
    if (tid < KSEL) { sv[tid] = g_vals[row * KSEL + tid]; si[tid] = g_idx[row * KSEL + tid]; }
    __syncthreads();

    float acc[16];
#pragma unroll
    for (int q = 0; q < 16; q++) acc[q] = 0.0f;

    for (int j = 0; j < KSEL; j++) {
        float v = sv[j];
        const uint4* wp = (const uint4*)(g_wdecT + (size_t)si[j] * IN_DIM);
#pragma unroll
        for (int w = 0; w < 2; w++) {
            uint4 t = wp[tid + w * 256];
            float2 f0 = __half22float2(*(__half2*)&t.x);
            float2 f1 = __half22float2(*(__half2*)&t.y);
            float2 f2 = __half22float2(*(__half2*)&t.z);
            float2 f3 = __half22float2(*(__half2*)&t.w);
            acc[w*8+0] = fmaf(v, f0.x, acc[w*8+0]);
            acc[w*8+1] = fmaf(v, f0.y, acc[w*8+1]);
            acc[w*8+2] = fmaf(v, f1.x, acc[w*8+2]);
            acc[w*8+3] = fmaf(v, f1.y, acc[w*8+3]);
            acc[w*8+4] = fmaf(v, f2.x, acc[w*8+4]);
            acc[w*8+5] = fmaf(v, f2.y, acc[w*8+5]);
            acc[w*8+6] = fmaf(v, f3.x, acc[w*8+6]);
            acc[w*8+7] = fmaf(v, f3.y, acc[w*8+7]);
        }
    }
    float* op = out_rec + (size_t)row * IN_DIM;
#pragma unroll
    for (int w = 0; w < 2; w++) {
        *(float4*)(op + (tid + w * 256) * 8)     = *(float4*)(&acc[w*8]);
        *(float4*)(op + (tid + w * 256) * 8 + 4) = *(float4*)(&acc[w*8+4]);
    }
}

// ============================================================================
// launch
// ============================================================================
extern "C" void kernel_launch(void* const* d_in, const int* in_sizes, int n_in,
                              void* d_out, int out_size)
{
    const float* x     = (const float*)d_in[0];
    const float* W_enc = (const float*)d_in[1];
    const float* b_enc = (const float*)d_in[2];
    const float* W_dec = (const float*)d_in[3];

    float* out_sf  = (float*)d_out;
    float* out_rec = out_sf + (size_t)BATCH * HID;

    __half *xh, *wh;
    cudaGetSymbolAddress((void**)&xh, g_xh);
    cudaGetSymbolAddress((void**)&wh, g_wh);

    // 1) fp16 conversions
    size_t nx4 = (size_t)BATCH * IN_DIM / 4;
    size_t nw4 = (size_t)HID * IN_DIM / 4;
    to_half_kernel<<<(unsigned)(nx4 / 256), 256>>>(x, xh, nx4);
    to_half_kernel<<<(unsigned)(nw4 / 256), 256>>>(W_enc, wh, nw4);

    // 2) transpose W_dec -> fp16
    wdec_transpose<<<dim3(HID / 32, IN_DIM / 32), dim3(32, 8)>>>(W_dec);

    // 3) approx encoder GEMM (HMMA, 2 CTAs/SM) -> out_sf
    cudaFuncSetAttribute(encoder_gemm_hmma, cudaFuncAttributeMaxDynamicSharedMemorySize,
                         GEMM_SMEM);
    encoder_gemm_hmma<<<(HID / GBN) * (BATCH / GBM), GEMM_THREADS, GEMM_SMEM>>>(b_enc, out_sf);

    // 4) top-k v4 (in-kernel histogram) + high-MLP exact refinement
    topk_kernel<<<BATCH, TOPK_THREADS>>>(out_sf, x, W_enc, b_enc);

    // 5) sparse decode (fp16 weights)
    decoder_kernel<<<BATCH, 256>>>(out_rec);
}

// round 15
// speedup vs baseline: 1.1068x; 1.0583x over previous
#include <cuda_runtime.h>
#include <cuda_fp16.h>
#include <cstdint>
#include <cstddef>

#define BATCH   8192
#define IN_DIM  4096
#define HID     16384
#define KSEL    64

// -------- scratch (allocation-free: __device__ globals) --------
__device__ __half g_wdecT[(size_t)HID * IN_DIM];     // W_dec^T in fp16 [HID, IN_DIM]
__device__ float  g_vals[BATCH * KSEL];
__device__ int    g_idx [BATCH * KSEL];
__device__ __half g_xh[(size_t)BATCH * IN_DIM];      // fp16(x)
__device__ __half g_wh[(size_t)HID * IN_DIM];        // fp16(W_enc)

// ============================================================================
// fp32 -> fp16 conversion
// ============================================================================
__global__ __launch_bounds__(256) void to_half_kernel(
    const float* __restrict__ src, __half* __restrict__ dst, size_t n4)
{
    size_t i = (size_t)blockIdx.x * 256 + threadIdx.x;
    if (i >= n4) return;
    float4 v = ((const float4*)src)[i];
    __half2* d = (__half2*)dst;
    d[2 * i]     = __floats2half2_rn(v.x, v.y);
    d[2 * i + 1] = __floats2half2_rn(v.z, v.w);
}

// ============================================================================
// transpose W_dec [IN_DIM, HID] -> g_wdecT (fp16) [HID, IN_DIM]
// ============================================================================
__global__ void wdec_transpose(const float* __restrict__ W)
{
    __shared__ float tile[32][33];
    int h0 = blockIdx.x * 32;
    int d0 = blockIdx.y * 32;
    int tx = threadIdx.x, ty = threadIdx.y;
#pragma unroll
    for (int r = 0; r < 32; r += 8)
        tile[ty + r][tx] = W[(size_t)(d0 + ty + r) * HID + (h0 + tx)];
    __syncthreads();
#pragma unroll
    for (int r = 0; r < 32; r += 8)
        g_wdecT[(size_t)(h0 + ty + r) * IN_DIM + (d0 + tx)] =
            __float2half_rn(tile[tx][ty + r]);
}

// ============================================================================
// Encoder GEMM: fp16 HMMA, fp32 accum (R11/R14 proven config — unchanged)
// ============================================================================
#define GBM 128
#define GBN 128
#define GBK 64
#define NSTAGE 3
#define ROWB 144
#define A_ST_B (GBM * ROWB)
#define B_ST_B (GBN * ROWB)
#define STG_B  (A_ST_B + B_ST_B)
#define GEMM_SMEM (NSTAGE * STG_B)   // 110592
#define K_ITERS (IN_DIM / GBK)
#define GEMM_THREADS 256

__device__ __forceinline__ uint32_t smem_u32(const void* p) {
    uint32_t a;
    asm("{ .reg .u64 t; cvta.to.shared.u64 t, %1; cvt.u32.u64 %0, t; }" : "=r"(a) : "l"(p));
    return a;
}
#define CP_ASYNC16(dst, src) \
    asm volatile("cp.async.cg.shared.global [%0], [%1], 16;" :: "r"(dst), "l"(src))
#define CP_COMMIT() asm volatile("cp.async.commit_group;" ::: "memory")
#define CP_WAIT1()  asm volatile("cp.async.wait_group 1;" ::: "memory")

#define LDSM_X4(r0, r1, r2, r3, addr) \
    asm volatile("ldmatrix.sync.aligned.m8n8.x4.shared.b16 {%0,%1,%2,%3}, [%4];" \
                 : "=r"(r0), "=r"(r1), "=r"(r2), "=r"(r3) : "r"(addr))

#define MMA16816(d, a, b0, b1) \
    asm volatile("mma.sync.aligned.m16n8k16.row.col.f32.f16.f16.f32 " \
                 "{%0,%1,%2,%3}, {%4,%5,%6,%7}, {%8,%9}, {%0,%1,%2,%3};" \
                 : "+f"((d)[0]), "+f"((d)[1]), "+f"((d)[2]), "+f"((d)[3]) \
                 : "r"((a)[0]), "r"((a)[1]), "r"((a)[2]), "r"((a)[3]), \
                   "r"(b0), "r"(b1))

__device__ __forceinline__ void gemm_load_stage(uint32_t sbase, int stage, int k0,
                                                int m0, int n0, int tid)
{
    uint32_t sb = sbase + stage * STG_B;
#pragma unroll
    for (int t = 0; t < 4; t++) {
        int i = tid + t * GEMM_THREADS;
        int row = i >> 3, c = i & 7;
        const __half* src = g_xh + (size_t)(m0 + row) * IN_DIM + k0 + c * 8;
        CP_ASYNC16(sb + row * ROWB + c * 16, src);
    }
    uint32_t sbB = sb + A_ST_B;
#pragma unroll
    for (int t = 0; t < 4; t++) {
        int i = tid + t * GEMM_THREADS;
        int row = i >> 3, c = i & 7;
        const __half* src = g_wh + (size_t)(n0 + row) * IN_DIM + k0 + c * 8;
        CP_ASYNC16(sbB + row * ROWB + c * 16, src);
    }
}

__global__ __launch_bounds__(GEMM_THREADS, 2) void encoder_gemm_hmma(
    const float* __restrict__ bias, float* __restrict__ out_sf)
{
    extern __shared__ __align__(128) char smem[];
    uint32_t sbase = smem_u32(smem);
    const int tid  = threadIdx.x;
    const int lane = tid & 31;
    const int wid  = tid >> 5;
    const int warp_m = wid & 1;
    const int warp_n = wid >> 1;

    int pid = blockIdx.x;
    int nb = (pid >> 3) & 127;
    int mb = (pid & 7) | ((pid >> 10) << 3);
    int m0 = mb * GBM, n0 = nb * GBN;

    const int g = lane >> 3;
    const int rA = warp_m * 64 + ((g & 1) << 3) + (lane & 7);
    const int cA = (g >> 1) << 4;
    const int rB = warp_n * 32 + ((g >> 1) << 3) + (lane & 7);
    const int cB = (g & 1) << 4;

    float acc[4][4][4];
#pragma unroll
    for (int i = 0; i < 4; i++)
#pragma unroll
        for (int j = 0; j < 4; j++)
#pragma unroll
            for (int q = 0; q < 4; q++) acc[i][j][q] = 0.0f;

    gemm_load_stage(sbase, 0, 0, m0, n0, tid); CP_COMMIT();
    gemm_load_stage(sbase, 1, GBK, m0, n0, tid); CP_COMMIT();

    for (int it = 0; it < K_ITERS; it++) {
        int cur = it % 3;
        CP_WAIT1();
        __syncthreads();

        if (it + 2 < K_ITERS)
            gemm_load_stage(sbase, (it + 2) % 3, (it + 2) * GBK, m0, n0, tid);
        CP_COMMIT();

        uint32_t aST = sbase + cur * STG_B;
        uint32_t bST = aST + A_ST_B;

#pragma unroll
        for (int ks = 0; ks < 4; ks++) {
            uint32_t koff = (uint32_t)(ks * 32);
            uint32_t af[4][4], bf[2][4];
#pragma unroll
            for (int mf = 0; mf < 4; mf++) {
                uint32_t ad = aST + (uint32_t)((rA + mf * 16) * ROWB + cA) + koff;
                LDSM_X4(af[mf][0], af[mf][1], af[mf][2], af[mf][3], ad);
            }
#pragma unroll
            for (int nf = 0; nf < 2; nf++) {
                uint32_t bd = bST + (uint32_t)((rB + nf * 16) * ROWB + cB) + koff;
                LDSM_X4(bf[nf][0], bf[nf][1], bf[nf][2], bf[nf][3], bd);
            }
#pragma unroll
            for (int mf = 0; mf < 4; mf++)
#pragma unroll
                for (int nf = 0; nf < 2; nf++) {
                    MMA16816(acc[mf][nf * 2],     af[mf], bf[nf][0], bf[nf][1]);
                    MMA16816(acc[mf][nf * 2 + 1], af[mf], bf[nf][2], bf[nf][3]);
                }
        }
    }

    int rbase = m0 + warp_m * 64 + (lane >> 2);
    int cbase = n0 + warp_n * 32 + ((lane & 3) << 1);
#pragma unroll
    for (int mf = 0; mf < 4; mf++) {
#pragma unroll
        for (int nf = 0; nf < 4; nf++) {
            int col = cbase + nf * 8;
            float b0 = __ldg(&bias[col]);
            float b1 = __ldg(&bias[col + 1]);
            int r0 = rbase + mf * 16;
            float2 v0, v1;
            v0.x = fmaxf(acc[mf][nf][0] + b0, 0.0f);
            v0.y = fmaxf(acc[mf][nf][1] + b1, 0.0f);
            v1.x = fmaxf(acc[mf][nf][2] + b0, 0.0f);
            v1.y = fmaxf(acc[mf][nf][3] + b1, 0.0f);
            *(float2*)(out_sf + (size_t)r0 * HID + col)       = v0;
            *(float2*)(out_sf + (size_t)(r0 + 8) * HID + col) = v1;
        }
    }
}

// ============================================================================
// top-k v6: occupancy-bounded (>=3 CTAs/SM), 2048-bin histogram (bracket
//   2^-10 rel -> narrower zone, fewer refines), moderate-MLP refinement.
// ============================================================================
#define TOPK_THREADS 512
#define NBINS 2048
#define ERRB 3e-3f
#define ZCAP 128
#define NWORDS (HID / 32)    // 512

__device__ __forceinline__ float refine_dot_warp(const float* __restrict__ xr,
                                                 const float* __restrict__ wr,
                                                 float b, int lane)
{
    const float4* x4 = (const float4*)xr;
    const float4* w4 = (const float4*)wr;
    float s = 0.f, c = 0.f;
#pragma unroll
    for (int t = 0; t < 16; t++) {
        float4 xa[2], wa[2];
#pragma unroll
        for (int q = 0; q < 2; q++) {
            int idx = lane + (t * 2 + q) * 32;
            xa[q] = x4[idx];
            wa[q] = w4[idx];
        }
        float r = xa[0].x * wa[0].x;
        r = fmaf(xa[0].y, wa[0].y, r);
        r = fmaf(xa[0].z, wa[0].z, r);
        r = fmaf(xa[0].w, wa[0].w, r);
        r = fmaf(xa[1].x, wa[1].x, r);
        r = fmaf(xa[1].y, wa[1].y, r);
        r = fmaf(xa[1].z, wa[1].z, r);
        r = fmaf(xa[1].w, wa[1].w, r);
        float tt = s + r;
        float z = tt - s;
        float e = (s - (tt - z)) + (r - z);
        c += e; s = tt;
    }
#pragma unroll
    for (int off = 16; off; off >>= 1) {
        float s2 = __shfl_down_sync(0xffffffffu, s, off);
        float c2 = __shfl_down_sync(0xffffffffu, c, off);
        float tt = s + s2;
        float z = tt - s;
        float e = (s - (tt - z)) + (s2 - z);
        c += c2 + e; s = tt;
    }
    float d = s + c;
    return fmaxf(d + b, 0.0f);
}

__device__ __forceinline__ int scan_bins_top(const uint32_t* hist, int top,
                                             int base, int lane)
{
    int dbin = -1;
    int nrounds = (top + 31) / 32;
    for (int r = 0; r < nrounds; r++) {
        int bin = top - 1 - (r * 32 + lane);
        int h = (bin >= 0) ? (int)hist[bin] : 0;
        int pre = h;
#pragma unroll
        for (int off = 1; off < 32; off <<= 1) {
            int t = __shfl_up_sync(0xffffffffu, pre, off);
            if (lane >= off) pre += t;
        }
        int cum = base + pre;
        unsigned bal = __ballot_sync(0xffffffffu, (cum >= KSEL) && (bin >= 0));
        if (bal) {
            int l0 = __ffs(bal) - 1;
            dbin = top - 1 - (r * 32 + l0);
            break;
        }
        base += __shfl_sync(0xffffffffu, pre, 31);
    }
    return dbin;
}

__global__ __launch_bounds__(TOPK_THREADS, 3) void topk_kernel(
    float* __restrict__ out_sf,
    const float* __restrict__ x,
    const float* __restrict__ W,
    const float* __restrict__ bias)
{
    __shared__ uint32_t hist[NBINS];
    __shared__ uint32_t keep[NWORDS];
    __shared__ int s_big, s_nhi, s_nzone, s_dbin, s_mode;
    __shared__ int   s_zidx[ZCAP];
    __shared__ float s_zval[ZCAP];
    __shared__ unsigned char s_keepz[ZCAP];
    __shared__ int s_wsum[16];

    int row = blockIdx.x;
    int tid = threadIdx.x;
    int wid = tid >> 5, lane = tid & 31;
    float* orow = out_sf + (size_t)row * HID;

#pragma unroll
    for (int q = 0; q < NBINS / TOPK_THREADS; q++)
        hist[tid + q * TOPK_THREADS] = 0;
    if (tid == 0) { s_big = 0; s_nhi = 0; s_nzone = 0; s_dbin = -1; s_mode = 0; }
    __syncthreads();

    // sweep 1: read row (coalesced float4, DRAM) + 2048-bin histogram on [2,8)
    int mybig = 0;
#pragma unroll
    for (int t = 0; t < 8; t++) {
        float4 v4 = ((const float4*)orow)[tid + t * TOPK_THREADS];
        float vv[4] = {v4.x, v4.y, v4.z, v4.w};
#pragma unroll
        for (int c = 0; c < 4; c++) {
            float f = vv[c];
            if (f >= 8.0f) mybig++;
            else if (f >= 2.0f)
                atomicAdd(&hist[(__float_as_uint(f) >> 13) - 0x20000u], 1u);
        }
    }
#pragma unroll
    for (int off = 16; off; off >>= 1) mybig += __shfl_down_sync(0xffffffffu, mybig, off);
    if (lane == 0 && mybig) atomicAdd(&s_big, mybig);
    __syncthreads();

    if (wid == 0) {
        int d = scan_bins_top(hist, 2048, s_big, lane);
        if (lane == 0) { s_dbin = d; if (d >= 0) s_mode = 1; }
    }
    __syncthreads();

    if (s_mode == 0) {
        // mode B (rare): histogram [0.25, 8) on bits[30:16]
#pragma unroll
        for (int q = 0; q < NBINS / TOPK_THREADS; q++)
            hist[tid + q * TOPK_THREADS] = 0;
        __syncthreads();
        for (int i = tid; i < HID; i += TOPK_THREADS) {
            float f = orow[i];
            if (f >= 0.25f && f < 8.0f)
                atomicAdd(&hist[(__float_as_uint(f) >> 16) - 0x3E80u], 1u);
        }
        __syncthreads();
        if (wid == 0) {
            int d = scan_bins_top(hist, 640, s_big, lane);
            if (lane == 0) { s_dbin = d; if (d >= 0) s_mode = 2; else s_mode = 3; }
        }
        __syncthreads();
    }

    float B_lo, B_hi;
    if (s_mode == 1) {
        B_lo = __uint_as_float((uint32_t)(0x20000u + s_dbin) << 13);
        B_hi = __uint_as_float((uint32_t)(0x20000u + s_dbin + 1) << 13);
    } else if (s_mode == 2) {
        B_lo = __uint_as_float((uint32_t)(0x3E80u + s_dbin) << 16);
        B_hi = __uint_as_float((uint32_t)(0x3E80u + s_dbin + 1) << 16);
    } else {
        B_lo = 0.0f; B_hi = 0.25f;
    }
    float Thi = B_hi + 2.0f * ERRB;
    float Tlo = B_lo - 2.0f * ERRB;

    // sweep 2 (L2-hot): classify + zero below-zone positives + provisional keep
    {
        int myhi = 0;
        for (int w = wid; w < NWORDS; w += (TOPK_THREADS / 32)) {
            int i = w * 32 + lane;
            float f = orow[i];
            bool hi = (f > Thi);
            bool inz = false;
            if (!hi && f > 0.0f && f >= Tlo) {
                int p = atomicAdd(&s_nzone, 1);
                if (p < ZCAP) { s_zidx[p] = i; s_zval[p] = f; inz = true; }
            }
            myhi += hi;
            unsigned m = __ballot_sync(0xffffffffu, hi);
            if (lane == 0) keep[w] = m;
            if (!hi && !inz && __float_as_uint(f) != 0u) orow[i] = 0.0f;
        }
#pragma unroll
        for (int off = 16; off; off >>= 1) myhi += __shfl_down_sync(0xffffffffu, myhi, off);
        if (lane == 0 && myhi) atomicAdd(&s_nhi, myhi);
    }
    __syncthreads();

    int nhi  = s_nhi;
    int nzr  = s_nzone;
    bool ovf = (nzr > ZCAP);
    int nz   = ovf ? ZCAP : nzr;
    int need = KSEL - nhi;

    bool did_refine = (!ovf && nz != need && nz > 0 && need > 0);
    if (did_refine) {
        const float* xr = x + (size_t)row * IN_DIM;
        for (int j = wid; j < nz; j += (TOPK_THREADS / 32)) {
            int h = s_zidx[j];
            float v = refine_dot_warp(xr, W + (size_t)h * IN_DIM, __ldg(&bias[h]), lane);
            if (lane == 0) s_zval[j] = v;
        }
    }
    __syncthreads();

    // rank selection among zone (exact top-`need`, index tiebreak)
    if (tid < nz) {
        bool km;
        if (!ovf && nz == need) km = true;
        else if (need <= 0) km = false;
        else {
            float mv = s_zval[tid]; int mi = s_zidx[tid];
            int better = 0;
            for (int j = 0; j < nz; j++) {
                if (j == tid) continue;
                if (s_zval[j] > mv || (s_zval[j] == mv && s_zidx[j] < mi)) better++;
            }
            km = (better < need);
        }
        s_keepz[tid] = km ? 1 : 0;
    }
    __syncthreads();

    // patch zone elements: kept -> (refined) value + keep bit; dropped -> 0
    if (tid < nz) {
        int i = s_zidx[tid];
        if (s_keepz[tid]) {
            orow[i] = s_zval[tid];
            atomicOr(&keep[i >> 5], 1u << (i & 31));
        } else {
            orow[i] = 0.0f;
        }
    }
    __syncthreads();

    // parallel compaction: block exclusive scan over keep-word popcounts
    {
        uint32_t m = keep[tid];
        int c = __popc(m);
        int pre = c;
#pragma unroll
        for (int off = 1; off < 32; off <<= 1) {
            int t = __shfl_up_sync(0xffffffffu, pre, off);
            if (lane >= off) pre += t;
        }
        if (lane == 31) s_wsum[wid] = pre;
        __syncthreads();
        if (wid == 0 && lane < 16) {
            int v = s_wsum[lane];
            int p = v;
#pragma unroll
            for (int off = 1; off < 16; off <<= 1) {
                int t = __shfl_up_sync(0xffffu, p, off);
                if (lane >= off) p += t;
            }
            s_wsum[lane] = p - v;
        }
        __syncthreads();
        int excl = s_wsum[wid] + pre - c;
        while (m) {
            int b = __ffs(m) - 1;
            m &= m - 1;
            if (excl < KSEL) {
                g_vals[row * KSEL + excl] = orow[tid * 32 + b];
                g_idx [row * KSEL + excl] = tid * 32 + b;
            }
            excl++;
        }
    }
}

// ============================================================================
// sparse decode  recon[b,:] = sum_j v_j * W_dec^T[h_j, :]  (fp16 weights)
// ============================================================================
__global__ __launch_bounds__(256) void decoder_kernel(float* __restrict__ out_rec)
{
    int row = blockIdx.x;
    int tid = threadIdx.x;
    __shared__ float sv[KSEL];
    __shared__ int   si[KSEL];
    if (tid < KSEL) { sv[tid] = g_vals[row * KSEL + tid]; si[tid] = g_idx[row * KSEL + tid]; }
    __syncthreads();

    float acc[16];
#pragma unroll
    for (int q = 0; q < 16; q++) acc[q] = 0.0f;

    for (int j = 0; j < KSEL; j++) {
        float v = sv[j];
        const uint4* wp = (const uint4*)(g_wdecT + (size_t)si[j] * IN_DIM);
#pragma unroll
        for (int w = 0; w < 2; w++) {
            uint4 t = wp[tid + w * 256];
            float2 f0 = __half22float2(*(__half2*)&t.x);
            float2 f1 = __half22float2(*(__half2*)&t.y);
            float2 f2 = __half22float2(*(__half2*)&t.z);
            float2 f3 = __half22float2(*(__half2*)&t.w);
            acc[w*8+0] = fmaf(v, f0.x, acc[w*8+0]);
            acc[w*8+1] = fmaf(v, f0.y, acc[w*8+1]);
            acc[w*8+2] = fmaf(v, f1.x, acc[w*8+2]);
            acc[w*8+3] = fmaf(v, f1.y, acc[w*8+3]);
            acc[w*8+4] = fmaf(v, f2.x, acc[w*8+4]);
            acc[w*8+5] = fmaf(v, f2.y, acc[w*8+5]);
            acc[w*8+6] = fmaf(v, f3.x, acc[w*8+6]);
            acc[w*8+7] = fmaf(v, f3.y, acc[w*8+7]);
        }
    }
    float* op = out_rec + (size_t)row * IN_DIM;
#pragma unroll
    for (int w = 0; w < 2; w++) {
        *(float4*)(op + (tid + w * 256) * 8)     = *(float4*)(&acc[w*8]);
        *(float4*)(op + (tid + w * 256) * 8 + 4) = *(float4*)(&acc[w*8+4]);
    }
}

// ============================================================================
// launch
// ============================================================================
extern "C" void kernel_launch(void* const* d_in, const int* in_sizes, int n_in,
                              void* d_out, int out_size)
{
    const float* x     = (const float*)d_in[0];
    const float* W_enc = (const float*)d_in[1];
    const float* b_enc = (const float*)d_in[2];
    const float* W_dec = (const float*)d_in[3];

    float* out_sf  = (float*)d_out;
    float* out_rec = out_sf + (size_t)BATCH * HID;

    __half *xh, *wh;
    cudaGetSymbolAddress((void**)&xh, g_xh);
    cudaGetSymbolAddress((void**)&wh, g_wh);

    // 1) fp16 conversions
    size_t nx4 = (size_t)BATCH * IN_DIM / 4;
    size_t nw4 = (size_t)HID * IN_DIM / 4;
    to_half_kernel<<<(unsigned)(nx4 / 256), 256>>>(x, xh, nx4);
    to_half_kernel<<<(unsigned)(nw4 / 256), 256>>>(W_enc, wh, nw4);

    // 2) transpose W_dec -> fp16
    wdec_transpose<<<dim3(HID / 32, IN_DIM / 32), dim3(32, 8)>>>(W_dec);

    // 3) approx encoder GEMM (HMMA, 2 CTAs/SM) -> out_sf
    cudaFuncSetAttribute(encoder_gemm_hmma, cudaFuncAttributeMaxDynamicSharedMemorySize,
                         GEMM_SMEM);
    encoder_gemm_hmma<<<(HID / GBN) * (BATCH / GBM), GEMM_THREADS, GEMM_SMEM>>>(b_enc, out_sf);

    // 4) top-k v6: occupancy-bounded, fine-grained bracket
    topk_kernel<<<BATCH, TOPK_THREADS>>>(out_sf, x, W_enc, b_enc);

    // 5) sparse decode (fp16 weights)
    decoder_kernel<<<BATCH, 256>>>(out_rec);
}

// round 16
// speedup vs baseline: 1.1143x; 1.0068x over previous
#include <cuda_runtime.h>
#include <cuda_fp16.h>
#include <cstdint>
#include <cstddef>

#define BATCH   8192
#define IN_DIM  4096
#define HID     16384
#define KSEL    64

// -------- scratch (allocation-free: __device__ globals) --------
__device__ __half g_wdecT[(size_t)HID * IN_DIM];     // W_dec^T in fp16 [HID, IN_DIM]
__device__ float  g_vals[BATCH * KSEL];
__device__ int    g_idx [BATCH * KSEL];
__device__ __half g_xh[(size_t)BATCH * IN_DIM];      // fp16(x)
__device__ __half g_wh[(size_t)HID * IN_DIM];        // fp16(W_enc)

// ============================================================================
// fp32 -> fp16 conversion
// ============================================================================
__global__ __launch_bounds__(256) void to_half_kernel(
    const float* __restrict__ src, __half* __restrict__ dst, size_t n4)
{
    size_t i = (size_t)blockIdx.x * 256 + threadIdx.x;
    if (i >= n4) return;
    float4 v = ((const float4*)src)[i];
    __half2* d = (__half2*)dst;
    d[2 * i]     = __floats2half2_rn(v.x, v.y);
    d[2 * i + 1] = __floats2half2_rn(v.z, v.w);
}

// ============================================================================
// transpose W_dec [IN_DIM, HID] -> g_wdecT (fp16) [HID, IN_DIM]
// ============================================================================
__global__ void wdec_transpose(const float* __restrict__ W)
{
    __shared__ float tile[32][33];
    int h0 = blockIdx.x * 32;
    int d0 = blockIdx.y * 32;
    int tx = threadIdx.x, ty = threadIdx.y;
#pragma unroll
    for (int r = 0; r < 32; r += 8)
        tile[ty + r][tx] = W[(size_t)(d0 + ty + r) * HID + (h0 + tx)];
    __syncthreads();
#pragma unroll
    for (int r = 0; r < 32; r += 8)
        g_wdecT[(size_t)(h0 + ty + r) * IN_DIM + (d0 + tx)] =
            __float2half_rn(tile[tx][ty + r]);
}

// ============================================================================
// Encoder GEMM v2: fp16 HMMA, fp32 accum
//   BM=128, BN=128, BK=64, 4 warps (2x2), warp tile 64x64 (higher
//   MMA/LDSM ratio -> smem no longer binding), 3-stage, 2 CTAs/SM.
// ============================================================================
#define GBM 128
#define GBN 128
#define GBK 64
#define NSTAGE 3
#define ROWB 144
#define A_ST_B (GBM * ROWB)
#define B_ST_B (GBN * ROWB)
#define STG_B  (A_ST_B + B_ST_B)
#define GEMM_SMEM (NSTAGE * STG_B)   // 110592
#define K_ITERS (IN_DIM / GBK)
#define GEMM_THREADS 128

__device__ __forceinline__ uint32_t smem_u32(const void* p) {
    uint32_t a;
    asm("{ .reg .u64 t; cvta.to.shared.u64 t, %1; cvt.u32.u64 %0, t; }" : "=r"(a) : "l"(p));
    return a;
}
#define CP_ASYNC16(dst, src) \
    asm volatile("cp.async.cg.shared.global [%0], [%1], 16;" :: "r"(dst), "l"(src))
#define CP_COMMIT() asm volatile("cp.async.commit_group;" ::: "memory")
#define CP_WAIT1()  asm volatile("cp.async.wait_group 1;" ::: "memory")

#define LDSM_X4(r0, r1, r2, r3, addr) \
    asm volatile("ldmatrix.sync.aligned.m8n8.x4.shared.b16 {%0,%1,%2,%3}, [%4];" \
                 : "=r"(r0), "=r"(r1), "=r"(r2), "=r"(r3) : "r"(addr))

#define MMA16816(d, a, b0, b1) \
    asm volatile("mma.sync.aligned.m16n8k16.row.col.f32.f16.f16.f32 " \
                 "{%0,%1,%2,%3}, {%4,%5,%6,%7}, {%8,%9}, {%0,%1,%2,%3};" \
                 : "+f"((d)[0]), "+f"((d)[1]), "+f"((d)[2]), "+f"((d)[3]) \
                 : "r"((a)[0]), "r"((a)[1]), "r"((a)[2]), "r"((a)[3]), \
                   "r"(b0), "r"(b1))

__device__ __forceinline__ void gemm_load_stage(uint32_t sbase, int stage, int k0,
                                                int m0, int n0, int tid)
{
    uint32_t sb = sbase + stage * STG_B;
    // A: 128 rows x 8 chunks of 16B = 1024 / 128 threads = 8 each
#pragma unroll
    for (int t = 0; t < 8; t++) {
        int i = tid + t * GEMM_THREADS;
        int row = i >> 3, c = i & 7;
        const __half* src = g_xh + (size_t)(m0 + row) * IN_DIM + k0 + c * 8;
        CP_ASYNC16(sb + row * ROWB + c * 16, src);
    }
    uint32_t sbB = sb + A_ST_B;
#pragma unroll
    for (int t = 0; t < 8; t++) {
        int i = tid + t * GEMM_THREADS;
        int row = i >> 3, c = i & 7;
        const __half* src = g_wh + (size_t)(n0 + row) * IN_DIM + k0 + c * 8;
        CP_ASYNC16(sbB + row * ROWB + c * 16, src);
    }
}

__global__ __launch_bounds__(GEMM_THREADS, 2) void encoder_gemm_hmma(
    const float* __restrict__ bias, float* __restrict__ out_sf)
{
    extern __shared__ __align__(128) char smem[];
    uint32_t sbase = smem_u32(smem);
    const int tid  = threadIdx.x;
    const int lane = tid & 31;
    const int wid  = tid >> 5;          // 0..3
    const int warp_m = wid & 1;         // 0..1 -> 64-row half
    const int warp_n = wid >> 1;        // 0..1 -> 64-col half

    // supertile swizzle: 8 consecutive CTAs share one B tile (same nb)
    int pid = blockIdx.x;
    int nb = (pid >> 3) & 127;
    int mb = (pid & 7) | ((pid >> 10) << 3);
    int m0 = mb * GBM, n0 = nb * GBN;

    const int g = lane >> 3;
    const int rA = warp_m * 64 + ((g & 1) << 3) + (lane & 7);
    const int cA = (g >> 1) << 4;
    const int rB = warp_n * 64 + ((g >> 1) << 3) + (lane & 7);
    const int cB = (g & 1) << 4;

    float acc[4][8][4];
#pragma unroll
    for (int i = 0; i < 4; i++)
#pragma unroll
        for (int j = 0; j < 8; j++)
#pragma unroll
            for (int q = 0; q < 4; q++) acc[i][j][q] = 0.0f;

    gemm_load_stage(sbase, 0, 0, m0, n0, tid); CP_COMMIT();
    gemm_load_stage(sbase, 1, GBK, m0, n0, tid); CP_COMMIT();

    for (int it = 0; it < K_ITERS; it++) {
        int cur = it % 3;
        CP_WAIT1();
        __syncthreads();

        if (it + 2 < K_ITERS)
            gemm_load_stage(sbase, (it + 2) % 3, (it + 2) * GBK, m0, n0, tid);
        CP_COMMIT();

        uint32_t aST = sbase + cur * STG_B;
        uint32_t bST = aST + A_ST_B;

#pragma unroll
        for (int ks = 0; ks < 4; ks++) {
            uint32_t koff = (uint32_t)(ks * 32);
            uint32_t af[4][4], bf[4][4];
#pragma unroll
            for (int mf = 0; mf < 4; mf++) {
                uint32_t ad = aST + (uint32_t)((rA + mf * 16) * ROWB + cA) + koff;
                LDSM_X4(af[mf][0], af[mf][1], af[mf][2], af[mf][3], ad);
            }
#pragma unroll
            for (int nf = 0; nf < 4; nf++) {
                uint32_t bd = bST + (uint32_t)((rB + nf * 16) * ROWB + cB) + koff;
                LDSM_X4(bf[nf][0], bf[nf][1], bf[nf][2], bf[nf][3], bd);
            }
#pragma unroll
            for (int mf = 0; mf < 4; mf++)
#pragma unroll
                for (int nf = 0; nf < 4; nf++) {
                    MMA16816(acc[mf][nf * 2],     af[mf], bf[nf][0], bf[nf][1]);
                    MMA16816(acc[mf][nf * 2 + 1], af[mf], bf[nf][2], bf[nf][3]);
                }
        }
    }

    // epilogue: bias + relu -> out_sf
    int rbase = m0 + warp_m * 64 + (lane >> 2);
    int cbase = n0 + warp_n * 64 + ((lane & 3) << 1);
#pragma unroll
    for (int mf = 0; mf < 4; mf++) {
#pragma unroll
        for (int nf = 0; nf < 8; nf++) {
            int col = cbase + nf * 8;
            float b0 = __ldg(&bias[col]);
            float b1 = __ldg(&bias[col + 1]);
            int r0 = rbase + mf * 16;
            float2 v0, v1;
            v0.x = fmaxf(acc[mf][nf][0] + b0, 0.0f);
            v0.y = fmaxf(acc[mf][nf][1] + b1, 0.0f);
            v1.x = fmaxf(acc[mf][nf][2] + b0, 0.0f);
            v1.y = fmaxf(acc[mf][nf][3] + b1, 0.0f);
            *(float2*)(out_sf + (size_t)r0 * HID + col)       = v0;
            *(float2*)(out_sf + (size_t)(r0 + 8) * HID + col) = v1;
        }
    }
}

// ============================================================================
// top-k v6 (R15 proven): occupancy-bounded, 2048-bin histogram bracket,
//   exact boundary refinement — UNCHANGED.
// ============================================================================
#define TOPK_THREADS 512
#define NBINS 2048
#define ERRB 3e-3f
#define ZCAP 128
#define NWORDS (HID / 32)    // 512

__device__ __forceinline__ float refine_dot_warp(const float* __restrict__ xr,
                                                 const float* __restrict__ wr,
                                                 float b, int lane)
{
    const float4* x4 = (const float4*)xr;
    const float4* w4 = (const float4*)wr;
    float s = 0.f, c = 0.f;
#pragma unroll
    for (int t = 0; t < 16; t++) {
        float4 xa[2], wa[2];
#pragma unroll
        for (int q = 0; q < 2; q++) {
            int idx = lane + (t * 2 + q) * 32;
            xa[q] = x4[idx];
            wa[q] = w4[idx];
        }
        float r = xa[0].x * wa[0].x;
        r = fmaf(xa[0].y, wa[0].y, r);
        r = fmaf(xa[0].z, wa[0].z, r);
        r = fmaf(xa[0].w, wa[0].w, r);
        r = fmaf(xa[1].x, wa[1].x, r);
        r = fmaf(xa[1].y, wa[1].y, r);
        r = fmaf(xa[1].z, wa[1].z, r);
        r = fmaf(xa[1].w, wa[1].w, r);
        float tt = s + r;
        float z = tt - s;
        float e = (s - (tt - z)) + (r - z);
        c += e; s = tt;
    }
#pragma unroll
    for (int off = 16; off; off >>= 1) {
        float s2 = __shfl_down_sync(0xffffffffu, s, off);
        float c2 = __shfl_down_sync(0xffffffffu, c, off);
        float tt = s + s2;
        float z = tt - s;
        float e = (s - (tt - z)) + (s2 - z);
        c += c2 + e; s = tt;
    }
    float d = s + c;
    return fmaxf(d + b, 0.0f);
}

__device__ __forceinline__ int scan_bins_top(const uint32_t* hist, int top,
                                             int base, int lane)
{
    int dbin = -1;
    int nrounds = (top + 31) / 32;
    for (int r = 0; r < nrounds; r++) {
        int bin = top - 1 - (r * 32 + lane);
        int h = (bin >= 0) ? (int)hist[bin] : 0;
        int pre = h;
#pragma unroll
        for (int off = 1; off < 32; off <<= 1) {
            int t = __shfl_up_sync(0xffffffffu, pre, off);
            if (lane >= off) pre += t;
        }
        int cum = base + pre;
        unsigned bal = __ballot_sync(0xffffffffu, (cum >= KSEL) && (bin >= 0));
        if (bal) {
            int l0 = __ffs(bal) - 1;
            dbin = top - 1 - (r * 32 + l0);
            break;
        }
        base += __shfl_sync(0xffffffffu, pre, 31);
    }
    return dbin;
}

__global__ __launch_bounds__(TOPK_THREADS, 3) void topk_kernel(
    float* __restrict__ out_sf,
    const float* __restrict__ x,
    const float* __restrict__ W,
    const float* __restrict__ bias)
{
    __shared__ uint32_t hist[NBINS];
    __shared__ uint32_t keep[NWORDS];
    __shared__ int s_big, s_nhi, s_nzone, s_dbin, s_mode;
    __shared__ int   s_zidx[ZCAP];
    __shared__ float s_zval[ZCAP];
    __shared__ unsigned char s_keepz[ZCAP];
    __shared__ int s_wsum[16];

    int row = blockIdx.x;
    int tid = threadIdx.x;
    int wid = tid >> 5, lane = tid & 31;
    float* orow = out_sf + (size_t)row * HID;

#pragma unroll
    for (int q = 0; q < NBINS / TOPK_THREADS; q++)
        hist[tid + q * TOPK_THREADS] = 0;
    if (tid == 0) { s_big = 0; s_nhi = 0; s_nzone = 0; s_dbin = -1; s_mode = 0; }
    __syncthreads();

    // sweep 1: read row (coalesced float4, DRAM) + 2048-bin histogram on [2,8)
    int mybig = 0;
#pragma unroll
    for (int t = 0; t < 8; t++) {
        float4 v4 = ((const float4*)orow)[tid + t * TOPK_THREADS];
        float vv[4] = {v4.x, v4.y, v4.z, v4.w};
#pragma unroll
        for (int c = 0; c < 4; c++) {
            float f = vv[c];
            if (f >= 8.0f) mybig++;
            else if (f >= 2.0f)
                atomicAdd(&hist[(__float_as_uint(f) >> 13) - 0x20000u], 1u);
        }
    }
#pragma unroll
    for (int off = 16; off; off >>= 1) mybig += __shfl_down_sync(0xffffffffu, mybig, off);
    if (lane == 0 && mybig) atomicAdd(&s_big, mybig);
    __syncthreads();

    if (wid == 0) {
        int d = scan_bins_top(hist, 2048, s_big, lane);
        if (lane == 0) { s_dbin = d; if (d >= 0) s_mode = 1; }
    }
    __syncthreads();

    if (s_mode == 0) {
        // mode B (rare): histogram [0.25, 8) on bits[30:16]
#pragma unroll
        for (int q = 0; q < NBINS / TOPK_THREADS; q++)
            hist[tid + q * TOPK_THREADS] = 0;
        __syncthreads();
        for (int i = tid; i < HID; i += TOPK_THREADS) {
            float f = orow[i];
            if (f >= 0.25f && f < 8.0f)
                atomicAdd(&hist[(__float_as_uint(f) >> 16) - 0x3E80u], 1u);
        }
        __syncthreads();
        if (wid == 0) {
            int d = scan_bins_top(hist, 640, s_big, lane);
            if (lane == 0) { s_dbin = d; if (d >= 0) s_mode = 2; else s_mode = 3; }
        }
        __syncthreads();
    }

    float B_lo, B_hi;
    if (s_mode == 1) {
        B_lo = __uint_as_float((uint32_t)(0x20000u + s_dbin) << 13);
        B_hi = __uint_as_float((uint32_t)(0x20000u + s_dbin + 1) << 13);
    } else if (s_mode == 2) {
        B_lo = __uint_as_float((uint32_t)(0x3E80u + s_dbin) << 16);
        B_hi = __uint_as_float((uint32_t)(0x3E80u + s_dbin + 1) << 16);
    } else {
        B_lo = 0.0f; B_hi = 0.25f;
    }
    float Thi = B_hi + 2.0f * ERRB;
    float Tlo = B_lo - 2.0f * ERRB;

    // sweep 2 (L2-hot): classify + zero below-zone positives + provisional keep
    {
        int myhi = 0;
        for (int w = wid; w < NWORDS; w += (TOPK_THREADS / 32)) {
            int i = w * 32 + lane;
            float f = orow[i];
            bool hi = (f > Thi);
            bool inz = false;
            if (!hi && f > 0.0f && f >= Tlo) {
                int p = atomicAdd(&s_nzone, 1);
                if (p < ZCAP) { s_zidx[p] = i; s_zval[p] = f; inz = true; }
            }
            myhi += hi;
            unsigned m = __ballot_sync(0xffffffffu, hi);
            if (lane == 0) keep[w] = m;
            if (!hi && !inz && __float_as_uint(f) != 0u) orow[i] = 0.0f;
        }
#pragma unroll
        for (int off = 16; off; off >>= 1) myhi += __shfl_down_sync(0xffffffffu, myhi, off);
        if (lane == 0 && myhi) atomicAdd(&s_nhi, myhi);
    }
    __syncthreads();

    int nhi  = s_nhi;
    int nzr  = s_nzone;
    bool ovf = (nzr > ZCAP);
    int nz   = ovf ? ZCAP : nzr;
    int need = KSEL - nhi;

    bool did_refine = (!ovf && nz != need && nz > 0 && need > 0);
    if (did_refine) {
        const float* xr = x + (size_t)row * IN_DIM;
        for (int j = wid; j < nz; j += (TOPK_THREADS / 32)) {
            int h = s_zidx[j];
            float v = refine_dot_warp(xr, W + (size_t)h * IN_DIM, __ldg(&bias[h]), lane);
            if (lane == 0) s_zval[j] = v;
        }
    }
    __syncthreads();

    // rank selection among zone (exact top-`need`, index tiebreak)
    if (tid < nz) {
        bool km;
        if (!ovf && nz == need) km = true;
        else if (need <= 0) km = false;
        else {
            float mv = s_zval[tid]; int mi = s_zidx[tid];
            int better = 0;
            for (int j = 0; j < nz; j++) {
                if (j == tid) continue;
                if (s_zval[j] > mv || (s_zval[j] == mv && s_zidx[j] < mi)) better++;
            }
            km = (better < need);
        }
        s_keepz[tid] = km ? 1 : 0;
    }
    __syncthreads();

    // patch zone elements: kept -> (refined) value + keep bit; dropped -> 0
    if (tid < nz) {
        int i = s_zidx[tid];
        if (s_keepz[tid]) {
            orow[i] = s_zval[tid];
            atomicOr(&keep[i >> 5], 1u << (i & 31));
        } else {
            orow[i] = 0.0f;
        }
    }
    __syncthreads();

    // parallel compaction: block exclusive scan over keep-word popcounts
    {
        uint32_t m = keep[tid];
        int c = __popc(m);
        int pre = c;
#pragma unroll
        for (int off = 1; off < 32; off <<= 1) {
            int t = __shfl_up_sync(0xffffffffu, pre, off);
            if (lane >= off) pre += t;
        }
        if (lane == 31) s_wsum[wid] = pre;
        __syncthreads();
        if (wid == 0 && lane < 16) {
            int v = s_wsum[lane];
            int p = v;
#pragma unroll
            for (int off = 1; off < 16; off <<= 1) {
                int t = __shfl_up_sync(0xffffu, p, off);
                if (lane >= off) p += t;
            }
            s_wsum[lane] = p - v;
        }
        __syncthreads();
        int excl = s_wsum[wid] + pre - c;
        while (m) {
            int b = __ffs(m) - 1;
            m &= m - 1;
            if (excl < KSEL) {
                g_vals[row * KSEL + excl] = orow[tid * 32 + b];
                g_idx [row * KSEL + excl] = tid * 32 + b;
            }
            excl++;
        }
    }
}

// ============================================================================
// sparse decode  recon[b,:] = sum_j v_j * W_dec^T[h_j, :]  (fp16 weights)
// ============================================================================
__global__ __launch_bounds__(256) void decoder_kernel(float* __restrict__ out_rec)
{
    int row = blockIdx.x;
    int tid = threadIdx.x;
    __shared__ float sv[KSEL];
    __shared__ int   si[KSEL];
    if (tid < KSEL) { sv[tid] = g_vals[row * KSEL + tid]; si[tid] = g_idx[row * KSEL + tid]; }
    __syncthreads();

    float acc[16];
#pragma unroll
    for (int q = 0; q < 16; q++) acc[q] = 0.0f;

    for (int j = 0; j < KSEL; j++) {
        float v = sv[j];
        const uint4* wp = (const uint4*)(g_wdecT + (size_t)si[j] * IN_DIM);
#pragma unroll
        for (int w = 0; w < 2; w++) {
            uint4 t = wp[tid + w * 256];
            float2 f0 = __half22float2(*(__half2*)&t.x);
            float2 f1 = __half22float2(*(__half2*)&t.y);
            float2 f2 = __half22float2(*(__half2*)&t.z);
            float2 f3 = __half22float2(*(__half2*)&t.w);
            acc[w*8+0] = fmaf(v, f0.x, acc[w*8+0]);
            acc[w*8+1] = fmaf(v, f0.y, acc[w*8+1]);
            acc[w*8+2] = fmaf(v, f1.x, acc[w*8+2]);
            acc[w*8+3] = fmaf(v, f1.y, acc[w*8+3]);
            acc[w*8+4] = fmaf(v, f2.x, acc[w*8+4]);
            acc[w*8+5] = fmaf(v, f2.y, acc[w*8+5]);
            acc[w*8+6] = fmaf(v, f3.x, acc[w*8+6]);
            acc[w*8+7] = fmaf(v, f3.y, acc[w*8+7]);
        }
    }
    float* op = out_rec + (size_t)row * IN_DIM;
#pragma unroll
    for (int w = 0; w < 2; w++) {
        *(float4*)(op + (tid + w * 256) * 8)     = *(float4*)(&acc[w*8]);
        *(float4*)(op + (tid + w * 256) * 8 + 4) = *(float4*)(&acc[w*8+4]);
    }
}

// ============================================================================
// launch
// ============================================================================
extern "C" void kernel_launch(void* const* d_in, const int* in_sizes, int n_in,
                              void* d_out, int out_size)
{
    const float* x     = (const float*)d_in[0];
    const float* W_enc = (const float*)d_in[1];
    const float* b_enc = (const float*)d_in[2];
    const float* W_dec = (const float*)d_in[3];

    float* out_sf  = (float*)d_out;
    float* out_rec = out_sf + (size_t)BATCH * HID;

    __half *xh, *wh;
    cudaGetSymbolAddress((void**)&xh, g_xh);
    cudaGetSymbolAddress((void**)&wh, g_wh);

    // 1) fp16 conversions
    size_t nx4 = (size_t)BATCH * IN_DIM / 4;
    size_t nw4 = (size_t)HID * IN_DIM / 4;
    to_half_kernel<<<(unsigned)(nx4 / 256), 256>>>(x, xh, nx4);
    to_half_kernel<<<(unsigned)(nw4 / 256), 256>>>(W_enc, wh, nw4);

    // 2) transpose W_dec -> fp16
    wdec_transpose<<<dim3(HID / 32, IN_DIM / 32), dim3(32, 8)>>>(W_dec);

    // 3) encoder GEMM v2 (64x64 warp tiles, 4 warps, 2 CTAs/SM) -> out_sf
    cudaFuncSetAttribute(encoder_gemm_hmma, cudaFuncAttributeMaxDynamicSharedMemorySize,
                         GEMM_SMEM);
    encoder_gemm_hmma<<<(HID / GBN) * (BATCH / GBM), GEMM_THREADS, GEMM_SMEM>>>(b_enc, out_sf);

    // 4) top-k v6 (R15 proven)
    topk_kernel<<<BATCH, TOPK_THREADS>>>(out_sf, x, W_enc, b_enc);

    // 5) sparse decode (fp16 weights)
    decoder_kernel<<<BATCH, 256>>>(out_rec);
}

// round 17
// speedup vs baseline: 1.1607x; 1.0416x over previous
#include <cuda_runtime.h>
#include <cuda_fp16.h>
#include <cstdint>
#include <cstddef>

#define BATCH   8192
#define IN_DIM  4096
#define HID     16384
#define KSEL    64

// -------- scratch (allocation-free: __device__ globals) --------
__device__ __half g_wdecT[(size_t)HID * IN_DIM];     // W_dec^T in fp16 [HID, IN_DIM]
__device__ float  g_vals[BATCH * KSEL];
__device__ int    g_idx [BATCH * KSEL];
__device__ __half g_xh[(size_t)BATCH * IN_DIM];      // fp16(x)
__device__ __half g_wh[(size_t)HID * IN_DIM];        // fp16(W_enc)

// ============================================================================
// fused fp32 -> fp16 conversion for x and W_enc (one launch)
// ============================================================================
__global__ __launch_bounds__(256) void to_half2_kernel(
    const float* __restrict__ xsrc, __half* __restrict__ xdst, size_t nx4,
    const float* __restrict__ wsrc, __half* __restrict__ wdst, size_t nw4)
{
    size_t i = (size_t)blockIdx.x * 256 + threadIdx.x;
    const float* src; __half* dst; size_t idx;
    if (i < nx4) { src = xsrc; dst = xdst; idx = i; }
    else if (i < nx4 + nw4) { src = wsrc; dst = wdst; idx = i - nx4; }
    else return;
    float4 v = ((const float4*)src)[idx];
    __half2* d = (__half2*)dst;
    d[2 * idx]     = __floats2half2_rn(v.x, v.y);
    d[2 * idx + 1] = __floats2half2_rn(v.z, v.w);
}

// ============================================================================
// transpose W_dec [IN_DIM, HID] -> g_wdecT (fp16) [HID, IN_DIM]
// ============================================================================
__global__ void wdec_transpose(const float* __restrict__ W)
{
    __shared__ float tile[32][33];
    int h0 = blockIdx.x * 32;
    int d0 = blockIdx.y * 32;
    int tx = threadIdx.x, ty = threadIdx.y;
#pragma unroll
    for (int r = 0; r < 32; r += 8)
        tile[ty + r][tx] = W[(size_t)(d0 + ty + r) * HID + (h0 + tx)];
    __syncthreads();
#pragma unroll
    for (int r = 0; r < 32; r += 8)
        g_wdecT[(size_t)(h0 + ty + r) * IN_DIM + (d0 + tx)] =
            __float2half_rn(tile[tx][ty + r]);
}

// ============================================================================
// Encoder GEMM v2 (R16 best: 64x64 warp tiles, 4 warps, 2 CTAs/SM) — UNCHANGED
// ============================================================================
#define GBM 128
#define GBN 128
#define GBK 64
#define NSTAGE 3
#define ROWB 144
#define A_ST_B (GBM * ROWB)
#define B_ST_B (GBN * ROWB)
#define STG_B  (A_ST_B + B_ST_B)
#define GEMM_SMEM (NSTAGE * STG_B)   // 110592
#define K_ITERS (IN_DIM / GBK)
#define GEMM_THREADS 128

__device__ __forceinline__ uint32_t smem_u32(const void* p) {
    uint32_t a;
    asm("{ .reg .u64 t; cvta.to.shared.u64 t, %1; cvt.u32.u64 %0, t; }" : "=r"(a) : "l"(p));
    return a;
}
#define CP_ASYNC16(dst, src) \
    asm volatile("cp.async.cg.shared.global [%0], [%1], 16;" :: "r"(dst), "l"(src))
#define CP_COMMIT() asm volatile("cp.async.commit_group;" ::: "memory")
#define CP_WAIT1()  asm volatile("cp.async.wait_group 1;" ::: "memory")

#define LDSM_X4(r0, r1, r2, r3, addr) \
    asm volatile("ldmatrix.sync.aligned.m8n8.x4.shared.b16 {%0,%1,%2,%3}, [%4];" \
                 : "=r"(r0), "=r"(r1), "=r"(r2), "=r"(r3) : "r"(addr))

#define MMA16816(d, a, b0, b1) \
    asm volatile("mma.sync.aligned.m16n8k16.row.col.f32.f16.f16.f32 " \
                 "{%0,%1,%2,%3}, {%4,%5,%6,%7}, {%8,%9}, {%0,%1,%2,%3};" \
                 : "+f"((d)[0]), "+f"((d)[1]), "+f"((d)[2]), "+f"((d)[3]) \
                 : "r"((a)[0]), "r"((a)[1]), "r"((a)[2]), "r"((a)[3]), \
                   "r"(b0), "r"(b1))

__device__ __forceinline__ void gemm_load_stage(uint32_t sbase, int stage, int k0,
                                                int m0, int n0, int tid)
{
    uint32_t sb = sbase + stage * STG_B;
#pragma unroll
    for (int t = 0; t < 8; t++) {
        int i = tid + t * GEMM_THREADS;
        int row = i >> 3, c = i & 7;
        const __half* src = g_xh + (size_t)(m0 + row) * IN_DIM + k0 + c * 8;
        CP_ASYNC16(sb + row * ROWB + c * 16, src);
    }
    uint32_t sbB = sb + A_ST_B;
#pragma unroll
    for (int t = 0; t < 8; t++) {
        int i = tid + t * GEMM_THREADS;
        int row = i >> 3, c = i & 7;
        const __half* src = g_wh + (size_t)(n0 + row) * IN_DIM + k0 + c * 8;
        CP_ASYNC16(sbB + row * ROWB + c * 16, src);
    }
}

__global__ __launch_bounds__(GEMM_THREADS, 2) void encoder_gemm_hmma(
    const float* __restrict__ bias, float* __restrict__ out_sf)
{
    extern __shared__ __align__(128) char smem[];
    uint32_t sbase = smem_u32(smem);
    const int tid  = threadIdx.x;
    const int lane = tid & 31;
    const int wid  = tid >> 5;
    const int warp_m = wid & 1;
    const int warp_n = wid >> 1;

    int pid = blockIdx.x;
    int nb = (pid >> 3) & 127;
    int mb = (pid & 7) | ((pid >> 10) << 3);
    int m0 = mb * GBM, n0 = nb * GBN;

    const int g = lane >> 3;
    const int rA = warp_m * 64 + ((g & 1) << 3) + (lane & 7);
    const int cA = (g >> 1) << 4;
    const int rB = warp_n * 64 + ((g >> 1) << 3) + (lane & 7);
    const int cB = (g & 1) << 4;

    float acc[4][8][4];
#pragma unroll
    for (int i = 0; i < 4; i++)
#pragma unroll
        for (int j = 0; j < 8; j++)
#pragma unroll
            for (int q = 0; q < 4; q++) acc[i][j][q] = 0.0f;

    gemm_load_stage(sbase, 0, 0, m0, n0, tid); CP_COMMIT();
    gemm_load_stage(sbase, 1, GBK, m0, n0, tid); CP_COMMIT();

    for (int it = 0; it < K_ITERS; it++) {
        int cur = it % 3;
        CP_WAIT1();
        __syncthreads();

        if (it + 2 < K_ITERS)
            gemm_load_stage(sbase, (it + 2) % 3, (it + 2) * GBK, m0, n0, tid);
        CP_COMMIT();

        uint32_t aST = sbase + cur * STG_B;
        uint32_t bST = aST + A_ST_B;

#pragma unroll
        for (int ks = 0; ks < 4; ks++) {
            uint32_t koff = (uint32_t)(ks * 32);
            uint32_t af[4][4], bf[4][4];
#pragma unroll
            for (int mf = 0; mf < 4; mf++) {
                uint32_t ad = aST + (uint32_t)((rA + mf * 16) * ROWB + cA) + koff;
                LDSM_X4(af[mf][0], af[mf][1], af[mf][2], af[mf][3], ad);
            }
#pragma unroll
            for (int nf = 0; nf < 4; nf++) {
                uint32_t bd = bST + (uint32_t)((rB + nf * 16) * ROWB + cB) + koff;
                LDSM_X4(bf[nf][0], bf[nf][1], bf[nf][2], bf[nf][3], bd);
            }
#pragma unroll
            for (int mf = 0; mf < 4; mf++)
#pragma unroll
                for (int nf = 0; nf < 4; nf++) {
                    MMA16816(acc[mf][nf * 2],     af[mf], bf[nf][0], bf[nf][1]);
                    MMA16816(acc[mf][nf * 2 + 1], af[mf], bf[nf][2], bf[nf][3]);
                }
        }
    }

    int rbase = m0 + warp_m * 64 + (lane >> 2);
    int cbase = n0 + warp_n * 64 + ((lane & 3) << 1);
#pragma unroll
    for (int mf = 0; mf < 4; mf++) {
#pragma unroll
        for (int nf = 0; nf < 8; nf++) {
            int col = cbase + nf * 8;
            float b0 = __ldg(&bias[col]);
            float b1 = __ldg(&bias[col + 1]);
            int r0 = rbase + mf * 16;
            float2 v0, v1;
            v0.x = fmaxf(acc[mf][nf][0] + b0, 0.0f);
            v0.y = fmaxf(acc[mf][nf][1] + b1, 0.0f);
            v1.x = fmaxf(acc[mf][nf][2] + b0, 0.0f);
            v1.y = fmaxf(acc[mf][nf][3] + b1, 0.0f);
            *(float2*)(out_sf + (size_t)r0 * HID + col)       = v0;
            *(float2*)(out_sf + (size_t)(r0 + 8) * HID + col) = v1;
        }
    }
}

// ============================================================================
// top-k v7: R15 structure + 4-warp cooperative refinement (4x shorter
//   critical path; deterministic TwoSum partial merge).
// ============================================================================
#define TOPK_THREADS 512
#define NBINS 2048
#define ERRB 3e-3f
#define ZCAP 128
#define NWORDS (HID / 32)    // 512

// one warp computes compensated partial dot over elements [part*1024,(part+1)*1024)
__device__ __forceinline__ void refine_partial(const float* __restrict__ xr,
                                               const float* __restrict__ wr,
                                               int part, int lane,
                                               float& s_out, float& c_out)
{
    const float4* x4 = (const float4*)xr + part * 256;
    const float4* w4 = (const float4*)wr + part * 256;
    float s = 0.f, c = 0.f;
#pragma unroll
    for (int t = 0; t < 4; t++) {
        float4 xa[2], wa[2];
#pragma unroll
        for (int q = 0; q < 2; q++) {
            int idx = lane + (t * 2 + q) * 32;
            xa[q] = x4[idx];
            wa[q] = w4[idx];
        }
        float r = xa[0].x * wa[0].x;
        r = fmaf(xa[0].y, wa[0].y, r);
        r = fmaf(xa[0].z, wa[0].z, r);
        r = fmaf(xa[0].w, wa[0].w, r);
        r = fmaf(xa[1].x, wa[1].x, r);
        r = fmaf(xa[1].y, wa[1].y, r);
        r = fmaf(xa[1].z, wa[1].z, r);
        r = fmaf(xa[1].w, wa[1].w, r);
        float tt = s + r;
        float z = tt - s;
        float e = (s - (tt - z)) + (r - z);
        c += e; s = tt;
    }
#pragma unroll
    for (int off = 16; off; off >>= 1) {
        float s2 = __shfl_down_sync(0xffffffffu, s, off);
        float c2 = __shfl_down_sync(0xffffffffu, c, off);
        float tt = s + s2;
        float z = tt - s;
        float e = (s - (tt - z)) + (s2 - z);
        c += c2 + e; s = tt;
    }
    s_out = s; c_out = c;
}

__device__ __forceinline__ int scan_bins_top(const uint32_t* hist, int top,
                                             int base, int lane)
{
    int dbin = -1;
    int nrounds = (top + 31) / 32;
    for (int r = 0; r < nrounds; r++) {
        int bin = top - 1 - (r * 32 + lane);
        int h = (bin >= 0) ? (int)hist[bin] : 0;
        int pre = h;
#pragma unroll
        for (int off = 1; off < 32; off <<= 1) {
            int t = __shfl_up_sync(0xffffffffu, pre, off);
            if (lane >= off) pre += t;
        }
        int cum = base + pre;
        unsigned bal = __ballot_sync(0xffffffffu, (cum >= KSEL) && (bin >= 0));
        if (bal) {
            int l0 = __ffs(bal) - 1;
            dbin = top - 1 - (r * 32 + l0);
            break;
        }
        base += __shfl_sync(0xffffffffu, pre, 31);
    }
    return dbin;
}

__global__ __launch_bounds__(TOPK_THREADS, 3) void topk_kernel(
    float* __restrict__ out_sf,
    const float* __restrict__ x,
    const float* __restrict__ W,
    const float* __restrict__ bias)
{
    __shared__ uint32_t hist[NBINS];
    __shared__ uint32_t keep[NWORDS];
    __shared__ int s_big, s_nhi, s_nzone, s_dbin, s_mode;
    __shared__ int   s_zidx[ZCAP];
    __shared__ float s_zval[ZCAP];
    __shared__ unsigned char s_keepz[ZCAP];
    __shared__ int s_wsum[16];
    __shared__ float s_ps[4][4], s_pc[4][4];

    int row = blockIdx.x;
    int tid = threadIdx.x;
    int wid = tid >> 5, lane = tid & 31;
    float* orow = out_sf + (size_t)row * HID;

#pragma unroll
    for (int q = 0; q < NBINS / TOPK_THREADS; q++)
        hist[tid + q * TOPK_THREADS] = 0;
    if (tid == 0) { s_big = 0; s_nhi = 0; s_nzone = 0; s_dbin = -1; s_mode = 0; }
    __syncthreads();

    // sweep 1: read row (coalesced float4, DRAM) + 2048-bin histogram on [2,8)
    int mybig = 0;
#pragma unroll
    for (int t = 0; t < 8; t++) {
        float4 v4 = ((const float4*)orow)[tid + t * TOPK_THREADS];
        float vv[4] = {v4.x, v4.y, v4.z, v4.w};
#pragma unroll
        for (int c = 0; c < 4; c++) {
            float f = vv[c];
            if (f >= 8.0f) mybig++;
            else if (f >= 2.0f)
                atomicAdd(&hist[(__float_as_uint(f) >> 13) - 0x20000u], 1u);
        }
    }
#pragma unroll
    for (int off = 16; off; off >>= 1) mybig += __shfl_down_sync(0xffffffffu, mybig, off);
    if (lane == 0 && mybig) atomicAdd(&s_big, mybig);
    __syncthreads();

    if (wid == 0) {
        int d = scan_bins_top(hist, 2048, s_big, lane);
        if (lane == 0) { s_dbin = d; if (d >= 0) s_mode = 1; }
    }
    __syncthreads();

    if (s_mode == 0) {
        // mode B (rare): histogram [0.25, 8) on bits[30:16]
#pragma unroll
        for (int q = 0; q < NBINS / TOPK_THREADS; q++)
            hist[tid + q * TOPK_THREADS] = 0;
        __syncthreads();
        for (int i = tid; i < HID; i += TOPK_THREADS) {
            float f = orow[i];
            if (f >= 0.25f && f < 8.0f)
                atomicAdd(&hist[(__float_as_uint(f) >> 16) - 0x3E80u], 1u);
        }
        __syncthreads();
        if (wid == 0) {
            int d = scan_bins_top(hist, 640, s_big, lane);
            if (lane == 0) { s_dbin = d; if (d >= 0) s_mode = 2; else s_mode = 3; }
        }
        __syncthreads();
    }

    float B_lo, B_hi;
    if (s_mode == 1) {
        B_lo = __uint_as_float((uint32_t)(0x20000u + s_dbin) << 13);
        B_hi = __uint_as_float((uint32_t)(0x20000u + s_dbin + 1) << 13);
    } else if (s_mode == 2) {
        B_lo = __uint_as_float((uint32_t)(0x3E80u + s_dbin) << 16);
        B_hi = __uint_as_float((uint32_t)(0x3E80u + s_dbin + 1) << 16);
    } else {
        B_lo = 0.0f; B_hi = 0.25f;
    }
    float Thi = B_hi + 2.0f * ERRB;
    float Tlo = B_lo - 2.0f * ERRB;

    // sweep 2 (L2-hot): classify + zero below-zone positives + provisional keep
    {
        int myhi = 0;
        for (int w = wid; w < NWORDS; w += (TOPK_THREADS / 32)) {
            int i = w * 32 + lane;
            float f = orow[i];
            bool hi = (f > Thi);
            bool inz = false;
            if (!hi && f > 0.0f && f >= Tlo) {
                int p = atomicAdd(&s_nzone, 1);
                if (p < ZCAP) { s_zidx[p] = i; s_zval[p] = f; inz = true; }
            }
            myhi += hi;
            unsigned m = __ballot_sync(0xffffffffu, hi);
            if (lane == 0) keep[w] = m;
            if (!hi && !inz && __float_as_uint(f) != 0u) orow[i] = 0.0f;
        }
#pragma unroll
        for (int off = 16; off; off >>= 1) myhi += __shfl_down_sync(0xffffffffu, myhi, off);
        if (lane == 0 && myhi) atomicAdd(&s_nhi, myhi);
    }
    __syncthreads();

    int nhi  = s_nhi;
    int nzr  = s_nzone;
    bool ovf = (nzr > ZCAP);
    int nz   = ovf ? ZCAP : nzr;
    int need = KSEL - nhi;

    bool did_refine = (!ovf && nz != need && nz > 0 && need > 0);
    if (did_refine) {
        const float* xr = x + (size_t)row * IN_DIM;
        int grp  = wid >> 2;     // 0..3 : zone-element group
        int part = wid & 3;      // 0..3 : quarter of the dot
        int rounds = (nz + 3) / 4;
        for (int r = 0; r < rounds; r++) {
            int j = r * 4 + grp;
            if (j < nz) {
                int h = s_zidx[j];
                float ps, pc;
                refine_partial(xr, W + (size_t)h * IN_DIM, part, lane, ps, pc);
                if (lane == 0) { s_ps[grp][part] = ps; s_pc[grp][part] = pc; }
            }
            __syncthreads();
            if (tid < 4) {
                int j2 = r * 4 + tid;
                if (j2 < nz) {
                    float s = s_ps[tid][0], c = s_pc[tid][0];
#pragma unroll
                    for (int p = 1; p < 4; p++) {
                        float sp = s_ps[tid][p];
                        float tt = s + sp;
                        float z = tt - s;
                        float e = (s - (tt - z)) + (sp - z);
                        c += s_pc[tid][p] + e; s = tt;
                    }
                    int h = s_zidx[j2];
                    s_zval[j2] = fmaxf((s + c) + __ldg(&bias[h]), 0.0f);
                }
            }
            __syncthreads();
        }
    }
    __syncthreads();

    // rank selection among zone (exact top-`need`, index tiebreak)
    if (tid < nz) {
        bool km;
        if (!ovf && nz == need) km = true;
        else if (need <= 0) km = false;
        else {
            float mv = s_zval[tid]; int mi = s_zidx[tid];
            int better = 0;
            for (int j = 0; j < nz; j++) {
                if (j == tid) continue;
                if (s_zval[j] > mv || (s_zval[j] == mv && s_zidx[j] < mi)) better++;
            }
            km = (better < need);
        }
        s_keepz[tid] = km ? 1 : 0;
    }
    __syncthreads();

    // patch zone elements: kept -> (refined) value + keep bit; dropped -> 0
    if (tid < nz) {
        int i = s_zidx[tid];
        if (s_keepz[tid]) {
            orow[i] = s_zval[tid];
            atomicOr(&keep[i >> 5], 1u << (i & 31));
        } else {
            orow[i] = 0.0f;
        }
    }
    __syncthreads();

    // parallel compaction: block exclusive scan over keep-word popcounts
    {
        uint32_t m = keep[tid];
        int c = __popc(m);
        int pre = c;
#pragma unroll
        for (int off = 1; off < 32; off <<= 1) {
            int t = __shfl_up_sync(0xffffffffu, pre, off);
            if (lane >= off) pre += t;
        }
        if (lane == 31) s_wsum[wid] = pre;
        __syncthreads();
        if (wid == 0 && lane < 16) {
            int v = s_wsum[lane];
            int p = v;
#pragma unroll
            for (int off = 1; off < 16; off <<= 1) {
                int t = __shfl_up_sync(0xffffu, p, off);
                if (lane >= off) p += t;
            }
            s_wsum[lane] = p - v;
        }
        __syncthreads();
        int excl = s_wsum[wid] + pre - c;
        while (m) {
            int b = __ffs(m) - 1;
            m &= m - 1;
            if (excl < KSEL) {
                g_vals[row * KSEL + excl] = orow[tid * 32 + b];
                g_idx [row * KSEL + excl] = tid * 32 + b;
            }
            excl++;
        }
    }
}

// ============================================================================
// sparse decode (fp16 weights), j-loop batched x4 for MLP
// ============================================================================
__global__ __launch_bounds__(256) void decoder_kernel(float* __restrict__ out_rec)
{
    int row = blockIdx.x;
    int tid = threadIdx.x;
    __shared__ float sv[KSEL];
    __shared__ int   si[KSEL];
    if (tid < KSEL) { sv[tid] = g_vals[row * KSEL + tid]; si[tid] = g_idx[row * KSEL + tid]; }
    __syncthreads();

    float acc[16];
#pragma unroll
    for (int q = 0; q < 16; q++) acc[q] = 0.0f;

    for (int j = 0; j < KSEL; j += 4) {
        float v0 = sv[j], v1 = sv[j+1], v2 = sv[j+2], v3 = sv[j+3];
        const uint4* p0 = (const uint4*)(g_wdecT + (size_t)si[j]   * IN_DIM);
        const uint4* p1 = (const uint4*)(g_wdecT + (size_t)si[j+1] * IN_DIM);
        const uint4* p2 = (const uint4*)(g_wdecT + (size_t)si[j+2] * IN_DIM);
        const uint4* p3 = (const uint4*)(g_wdecT + (size_t)si[j+3] * IN_DIM);
#pragma unroll
        for (int w = 0; w < 2; w++) {
            int off = tid + w * 256;
            uint4 t0 = p0[off];
            uint4 t1 = p1[off];
            uint4 t2 = p2[off];
            uint4 t3 = p3[off];
            const uint4* ts[4] = {&t0, &t1, &t2, &t3};
            float vs[4] = {v0, v1, v2, v3};
#pragma unroll
            for (int k = 0; k < 4; k++) {
                float2 f0 = __half22float2(*(__half2*)&ts[k]->x);
                float2 f1 = __half22float2(*(__half2*)&ts[k]->y);
                float2 f2 = __half22float2(*(__half2*)&ts[k]->z);
                float2 f3 = __half22float2(*(__half2*)&ts[k]->w);
                float v = vs[k];
                acc[w*8+0] = fmaf(v, f0.x, acc[w*8+0]);
                acc[w*8+1] = fmaf(v, f0.y, acc[w*8+1]);
                acc[w*8+2] = fmaf(v, f1.x, acc[w*8+2]);
                acc[w*8+3] = fmaf(v, f1.y, acc[w*8+3]);
                acc[w*8+4] = fmaf(v, f2.x, acc[w*8+4]);
                acc[w*8+5] = fmaf(v, f2.y, acc[w*8+5]);
                acc[w*8+6] = fmaf(v, f3.x, acc[w*8+6]);
                acc[w*8+7] = fmaf(v, f3.y, acc[w*8+7]);
            }
        }
    }
    float* op = out_rec + (size_t)row * IN_DIM;
#pragma unroll
    for (int w = 0; w < 2; w++) {
        *(float4*)(op + (tid + w * 256) * 8)     = *(float4*)(&acc[w*8]);
        *(float4*)(op + (tid + w * 256) * 8 + 4) = *(float4*)(&acc[w*8+4]);
    }
}

// ============================================================================
// launch
// ============================================================================
extern "C" void kernel_launch(void* const* d_in, const int* in_sizes, int n_in,
                              void* d_out, int out_size)
{
    const float* x     = (const float*)d_in[0];
    const float* W_enc = (const float*)d_in[1];
    const float* b_enc = (const float*)d_in[2];
    const float* W_dec = (const float*)d_in[3];

    float* out_sf  = (float*)d_out;
    float* out_rec = out_sf + (size_t)BATCH * HID;

    __half *xh, *wh;
    cudaGetSymbolAddress((void**)&xh, g_xh);
    cudaGetSymbolAddress((void**)&wh, g_wh);

    // 1) fused fp16 conversions (x + W_enc in one launch)
    size_t nx4 = (size_t)BATCH * IN_DIM / 4;
    size_t nw4 = (size_t)HID * IN_DIM / 4;
    to_half2_kernel<<<(unsigned)((nx4 + nw4 + 255) / 256), 256>>>(x, xh, nx4, W_enc, wh, nw4);

    // 2) transpose W_dec -> fp16
    wdec_transpose<<<dim3(HID / 32, IN_DIM / 32), dim3(32, 8)>>>(W_dec);

    // 3) encoder GEMM v2 (R16 best) -> out_sf
    cudaFuncSetAttribute(encoder_gemm_hmma, cudaFuncAttributeMaxDynamicSharedMemorySize,
                         GEMM_SMEM);
    encoder_gemm_hmma<<<(HID / GBN) * (BATCH / GBM), GEMM_THREADS, GEMM_SMEM>>>(b_enc, out_sf);

    // 4) top-k v7 (4-warp cooperative refinement)
    topk_kernel<<<BATCH, TOPK_THREADS>>>(out_sf, x, W_enc, b_enc);

    // 5) sparse decode (fp16 weights, batched loads)
    decoder_kernel<<<BATCH, 256>>>(out_rec);
}